// round 12
// baseline (speedup 1.0000x reference)
#include <cuda_runtime.h>
#include <cuda_fp16.h>
#include <math.h>

#define B 64
#define LS 256
#define M 4
#define LW 256
#define LY 128
#define HID 512
#define NSTEP 6
#define NS1 (NSTEP+1)
#define KC 8           // split-K chunks for hs

#define NPB    512     // persistent blocks (8 per batch), all resident
#define NB_HS  128
#define NB_ST  8
#define NB_FIN 64
#define OFF_ST  NB_HS           // stats blocks 128..135
#define OFF_FIN 160             // fin blocks 160..223

// ---------------- scratch (__device__ globals: no allocs allowed) ----------
__device__ float d_phi[B*LS];
__device__ float d_sre[B*LS];
__device__ float d_sim[B*LS];
__device__ float d_Gsr[B*LS*M];
__device__ float d_Gsi[B*LS*M];
__device__ float d_Hsr[B*LS*M];
__device__ float d_Hsi[B*LS*M];
__device__ float d_hsp[KC*B*HID];     // split-K partials of hs
__device__ float d_hsv[B*HID];        // combined hs (written by stats)
__device__ float d_wyW[B*M*HID];
__device__ float d_mu[M*HID];
__device__ float d_scale[M*HID];
__device__ __half d_G16[(size_t)B*LS*LS*M*2];   // packed [gr0..3, gi0..3], streamed
__device__ __half d_H16[(size_t)B*LS*LS*M*2];   // packed, L2-kept (evict_last loads)
__device__ int   d_mvc[NSTEP][B];     // per-b mv completion (8 blocks)
__device__ int   d_finc[NSTEP][B];    // per-b fin completion
__device__ int   d_hsc[NSTEP];
__device__ int   d_stc[NSTEP];

__device__ __forceinline__ int ld_acq(const int* p) {
    int v;
    asm volatile("ld.acquire.gpu.b32 %0, [%1];" : "=r"(v) : "l"(p));
    return v;
}
__device__ __forceinline__ void signal(int* p) {
    __threadfence();
    atomicAdd(p, 1);
}
__device__ __forceinline__ void wait_for(const int* p, int target) {
    #pragma unroll 1
    for (int k = 0; k < 64; k++)
        if (ld_acq(p) >= target) return;
    while (ld_acq(p) < target) __nanosleep(32);
}

// ---- 32-byte L2 eviction-priority loads (.v4.b64 — legal on sm_103a) ----
__device__ __forceinline__ ulonglong4 ld_el64(const __half* p) {   // keep in L2
    ulonglong4 v;
    asm volatile("ld.global.L2::evict_last.v4.b64 {%0,%1,%2,%3}, [%4];"
        : "=l"(v.x), "=l"(v.y), "=l"(v.z), "=l"(v.w) : "l"(p));
    return v;
}
__device__ __forceinline__ ulonglong4 ld_ef64(const __half* p) {   // stream
    ulonglong4 v;
    asm volatile("ld.global.L2::evict_first.v4.b64 {%0,%1,%2,%3}, [%4];"
        : "=l"(v.x), "=l"(v.y), "=l"(v.z), "=l"(v.w) : "l"(p));
    return v;
}

__device__ __forceinline__ uint4 pack8(float4 re, float4 im) {
    __half2 a = __floats2half2_rn(re.x, re.y);
    __half2 b = __floats2half2_rn(re.z, re.w);
    __half2 c = __floats2half2_rn(im.x, im.y);
    __half2 d = __floats2half2_rn(im.z, im.w);
    uint4 u;
    u.x = *reinterpret_cast<unsigned*>(&a);
    u.y = *reinterpret_cast<unsigned*>(&b);
    u.z = *reinterpret_cast<unsigned*>(&c);
    u.w = *reinterpret_cast<unsigned*>(&d);
    return u;
}

// unpack one packed 16B entry (as two u64) and accumulate matvec partials
__device__ __forceinline__ void upd16u(unsigned long long lo, unsigned long long hi,
                                       float sr, float si, float* ar, float* ai) {
    unsigned u0 = (unsigned)lo, u1 = (unsigned)(lo >> 32);
    unsigned u2 = (unsigned)hi, u3 = (unsigned)(hi >> 32);
    float2 r01 = __half22float2(*reinterpret_cast<__half2*>(&u0));
    float2 r23 = __half22float2(*reinterpret_cast<__half2*>(&u1));
    float2 i01 = __half22float2(*reinterpret_cast<__half2*>(&u2));
    float2 i23 = __half22float2(*reinterpret_cast<__half2*>(&u3));
    float rr[4] = {r01.x, r01.y, r23.x, r23.y};
    float ii[4] = {i01.x, i01.y, i23.x, i23.y};
    #pragma unroll
    for (int m = 0; m < 4; m++) {
        ar[m] += rr[m]*sr - ii[m]*si;
        ai[m] += rr[m]*si + ii[m]*sr;
    }
}

// ---- butterfly reductions: sum V distinct values across 32 lanes ----------
// bfly16: after call, lane (2q + {0,1}) holds total of value q (q = (lane>>1)&15)
__device__ __forceinline__ float bfly16(const float* v, int lane) {
    float a[8];
    #pragma unroll
    for (int q = 0; q < 8; q++) {
        float sel = (lane & 16) ? v[q] : v[q+8];
        float got = __shfl_xor_sync(0xffffffffu, sel, 16);
        a[q] = ((lane & 16) ? v[q+8] : v[q]) + got;
    }
    float c[4];
    #pragma unroll
    for (int q = 0; q < 4; q++) {
        float sel = (lane & 8) ? a[q] : a[q+4];
        float got = __shfl_xor_sync(0xffffffffu, sel, 8);
        c[q] = ((lane & 8) ? a[q+4] : a[q]) + got;
    }
    float e[2];
    #pragma unroll
    for (int q = 0; q < 2; q++) {
        float sel = (lane & 4) ? c[q] : c[q+2];
        float got = __shfl_xor_sync(0xffffffffu, sel, 4);
        e[q] = ((lane & 4) ? c[q+2] : c[q]) + got;
    }
    {
        float sel = (lane & 2) ? e[0] : e[1];
        float got = __shfl_xor_sync(0xffffffffu, sel, 2);
        float f = ((lane & 2) ? e[1] : e[0]) + got;
        f += __shfl_xor_sync(0xffffffffu, f, 1);
        return f;
    }
}

// bfly4: lane (8q + *) holds total of value q (q = (lane>>3)&3)
__device__ __forceinline__ float bfly4(const float* v, int lane) {
    float a[2];
    #pragma unroll
    for (int q = 0; q < 2; q++) {
        float sel = (lane & 16) ? v[q] : v[q+2];
        float got = __shfl_xor_sync(0xffffffffu, sel, 16);
        a[q] = ((lane & 16) ? v[q+2] : v[q]) + got;
    }
    float sel = (lane & 8) ? a[0] : a[1];
    float got = __shfl_xor_sync(0xffffffffu, sel, 8);
    float f = ((lane & 8) ? a[1] : a[0]) + got;
    f += __shfl_xor_sync(0xffffffffu, f, 4);
    f += __shfl_xor_sync(0xffffffffu, f, 2);
    f += __shfl_xor_sync(0xffffffffu, f, 1);
    return f;
}

// scatter-store one reduced matvec value (from bfly16) to the right array
__device__ __forceinline__ void store_red16(float red, int lane, int ob) {
    if ((lane & 1) == 0) {
        int q = (lane >> 1) & 15;
        int m = q & 3;
        int o = ob + m;
        int which = q >> 2;
        if      (which == 0) d_Gsr[o] = red;
        else if (which == 1) d_Gsi[o] = red;
        else if (which == 2) d_Hsr[o] = red;
        else                 d_Hsi[o] = red;
    }
}

// ---------------- init: phi/s0/out0 + wyW precompute + counter reset -------
__global__ void __launch_bounds__(HID) k_init(const float* __restrict__ phi, float* __restrict__ out,
                                              const float* __restrict__ wr, const float* __restrict__ wi,
                                              const float* __restrict__ y,  const float* __restrict__ W1,
                                              const float* __restrict__ b1) {
    int tid = threadIdx.x;
    if (blockIdx.x < B) {
        int b = blockIdx.x;
        if (b == 0) {
            for (int t = tid; t < NSTEP*B*2 + NSTEP*2; t += HID) {
                if      (t < NSTEP*B)          ((int*)d_mvc)[t] = 0;
                else if (t < 2*NSTEP*B)        ((int*)d_finc)[t - NSTEP*B] = 0;
                else if (t < 2*NSTEP*B+NSTEP)  d_hsc[t - 2*NSTEP*B] = 0;
                else                            d_stc[t - 2*NSTEP*B - NSTEP] = 0;
            }
        }
        if (tid < LS) {
            int idx = b*LS + tid;
            float p = phi[idx];
            d_phi[idx] = p;
            float sn, cs;
            sincosf(p, &sn, &cs);
            d_sre[idx] = cs;
            d_sim[idx] = sn;
            out[(b*NS1)*LS + tid] = cs;
            out[(size_t)B*NS1*LS + (b*NS1)*LS + tid] = sn;
        }
        return;
    }
    int b = blockIdx.x - B;
    __shared__ float4 wy[2*LW + LY];       // 640 x 4 m-values
    for (int d = tid; d < 2*LW + LY; d += HID) {
        float4 v;
        if (d < LW)            v = *reinterpret_cast<const float4*>(wr + (size_t)(b*LW + d)*M);
        else if (d < 2*LW)     v = *reinterpret_cast<const float4*>(wi + (size_t)(b*LW + (d - LW))*M);
        else                   v = *reinterpret_cast<const float4*>(y  + (size_t)(b*LY + (d - 2*LW))*M);
        wy[d] = v;
    }
    __syncthreads();
    float bb = b1[tid];
    float a0 = bb, a1 = bb, a2 = bb, a3 = bb;
    const float* w = W1 + (size_t)(2*LS)*HID + tid;   // rows 512..1151
    #pragma unroll 4
    for (int d = 0; d < 2*LW + LY; d++) {
        float wv = w[(size_t)d * HID];
        float4 q = wy[d];
        a0 += q.x*wv; a1 += q.y*wv; a2 += q.z*wv; a3 += q.w*wv;
    }
    d_wyW[(b*M + 0)*HID + tid] = a0;
    d_wyW[(b*M + 1)*HID + tid] = a1;
    d_wyW[(b*M + 2)*HID + tid] = a2;
    d_wyW[(b*M + 3)*HID + tid] = a3;
}

// ===================== persistent kernel: all 6 steps ========================
__global__ void __launch_bounds__(256, 4)
k_steps(const float* __restrict__ Gr, const float* __restrict__ Gi,
        const float* __restrict__ Hr, const float* __restrict__ Hi,
        const float* __restrict__ W1,
        const float* __restrict__ gamma, const float* __restrict__ beta,
        const float* __restrict__ W2,   const float* __restrict__ b2,
        float* __restrict__ out) {
    int tid = threadIdx.x;
    int bid = blockIdx.x;
    int warp = tid >> 5, lane = tid & 31;

    __shared__ float ssr[LS], ssi[LS];        // s cache (b_mv)
    __shared__ float sf[4][64];               // hs
    __shared__ float ssum[4][4][64], ssq[4][4][64]; // stats [m][bs][hh]
    __shared__ float wsum[8][16];             // fin
    __shared__ float ws[8][4];
    __shared__ float rho_s[4], fac[4], sgrS[4], sgiS[4], shrS[4], shiS[4];

    const int b_mv = bid >> 3;                // 8 blocks per batch
    const int k8   = bid & 7;

    for (int step = 0; step < NSTEP; step++) {
        // ------------------ hs (blocks 0..127) — runs first ----------------
        if (bid < NB_HS) {
            int kc = k8, bq = bid >> 3;
            if (step > 0) {
                if (tid == 0) {
                    #pragma unroll
                    for (int bb = 0; bb < 4; bb++)
                        wait_for(&d_finc[step-1][bq*4 + bb], 1);
                }
                __syncthreads();
            }
            {
                int bb = tid >> 6, dd = tid & 63;
                int b = bq*4 + bb, d = kc*64 + dd;
                sf[bb][dd] = (d < LS) ? d_sre[b*LS + d] : d_sim[b*LS + d - LS];
            }
            __syncthreads();
            float a0=0.f,a1=0.f,a2=0.f,a3=0.f;
            float c0=0.f,c1=0.f,c2=0.f,c3=0.f;
            const float* w = W1 + (size_t)(kc*64)*HID + tid;
            #pragma unroll 8
            for (int dd = 0; dd < 64; dd++) {
                float wv0 = w[(size_t)dd * HID];
                float wv1 = w[(size_t)dd * HID + 256];
                float s0 = sf[0][dd], s1 = sf[1][dd], s2 = sf[2][dd], s3 = sf[3][dd];
                a0 += s0*wv0; a1 += s1*wv0; a2 += s2*wv0; a3 += s3*wv0;
                c0 += s0*wv1; c1 += s1*wv1; c2 += s2*wv1; c3 += s3*wv1;
            }
            int b0 = bq*4;
            d_hsp[(kc*B + b0+0)*HID + tid] = a0;
            d_hsp[(kc*B + b0+1)*HID + tid] = a1;
            d_hsp[(kc*B + b0+2)*HID + tid] = a2;
            d_hsp[(kc*B + b0+3)*HID + tid] = a3;
            d_hsp[(kc*B + b0+0)*HID + tid + 256] = c0;
            d_hsp[(kc*B + b0+1)*HID + tid + 256] = c1;
            d_hsp[(kc*B + b0+2)*HID + tid + 256] = c2;
            d_hsp[(kc*B + b0+3)*HID + tid + 256] = c3;
            __syncthreads();
            if (tid == 0) signal(&d_hsc[step]);
        }

        // ------------------ mv: gate on own batch's fin (step-1) -----------
        if (step > 0) {
            if (tid == 0) wait_for(&d_finc[step-1][b_mv], 1);
            __syncthreads();
        }
        ssr[tid] = d_sre[b_mv*LS + tid];
        ssi[tid] = d_sim[b_mv*LS + tid];
        __syncthreads();

        if (step == 0) {
            // ---- fp32 read + fp16 convert-store + accumulate ----
            #pragma unroll 1
            for (int t4 = 0; t4 < 4; t4++) {
                int chunk = (bid*4 + t4) & 31;
                int i     = chunk*8 + warp;
                size_t base   = (size_t)(b_mv*LS + i) * (LS*M);
                size_t base16 = (size_t)(b_mv*LS + i) * LS * 8;   // halfs
                float gsr[4] = {0,0,0,0}, gsi[4] = {0,0,0,0};
                float hsr[4] = {0,0,0,0}, hsi[4] = {0,0,0,0};
                #pragma unroll
                for (int t = 0; t < 4; t++) {
                    int j0 = lane + t*64;
                    int j1 = j0 + 32;
                    float4 g_r0 = __ldcs(reinterpret_cast<const float4*>(Gr + base + (size_t)j0*M));
                    float4 g_i0 = __ldcs(reinterpret_cast<const float4*>(Gi + base + (size_t)j0*M));
                    float4 h_r0 = __ldcs(reinterpret_cast<const float4*>(Hr + base + (size_t)j0*M));
                    float4 h_i0 = __ldcs(reinterpret_cast<const float4*>(Hi + base + (size_t)j0*M));
                    float4 g_r1 = __ldcs(reinterpret_cast<const float4*>(Gr + base + (size_t)j1*M));
                    float4 g_i1 = __ldcs(reinterpret_cast<const float4*>(Gi + base + (size_t)j1*M));
                    float4 h_r1 = __ldcs(reinterpret_cast<const float4*>(Hr + base + (size_t)j1*M));
                    float4 h_i1 = __ldcs(reinterpret_cast<const float4*>(Hi + base + (size_t)j1*M));
                    // convert + store packed fp16: G streamed (stcs), H default prio
                    __stcs(reinterpret_cast<uint4*>(d_G16 + base16 + (size_t)j0*8), pack8(g_r0, g_i0));
                    __stcs(reinterpret_cast<uint4*>(d_G16 + base16 + (size_t)j1*8), pack8(g_r1, g_i1));
                    *reinterpret_cast<uint4*>(d_H16 + base16 + (size_t)j0*8) = pack8(h_r0, h_i0);
                    *reinterpret_cast<uint4*>(d_H16 + base16 + (size_t)j1*8) = pack8(h_r1, h_i1);
                    float sr0 = ssr[j0], si0 = ssi[j0];
                    float sr1 = ssr[j1], si1 = ssi[j1];
                    float grx[4] = {g_r0.x, g_r0.y, g_r0.z, g_r0.w};
                    float gix[4] = {g_i0.x, g_i0.y, g_i0.z, g_i0.w};
                    float hrx[4] = {h_r0.x, h_r0.y, h_r0.z, h_r0.w};
                    float hix[4] = {h_i0.x, h_i0.y, h_i0.z, h_i0.w};
                    float gry[4] = {g_r1.x, g_r1.y, g_r1.z, g_r1.w};
                    float giy[4] = {g_i1.x, g_i1.y, g_i1.z, g_i1.w};
                    float hry[4] = {h_r1.x, h_r1.y, h_r1.z, h_r1.w};
                    float hiy[4] = {h_i1.x, h_i1.y, h_i1.z, h_i1.w};
                    #pragma unroll
                    for (int m = 0; m < 4; m++) {
                        gsr[m] += grx[m]*sr0 - gix[m]*si0;
                        gsi[m] += grx[m]*si0 + gix[m]*sr0;
                        hsr[m] += hrx[m]*sr0 - hix[m]*si0;
                        hsi[m] += hrx[m]*si0 + hix[m]*sr0;
                        gsr[m] += gry[m]*sr1 - giy[m]*si1;
                        gsi[m] += gry[m]*si1 + giy[m]*sr1;
                        hsr[m] += hry[m]*sr1 - hiy[m]*si1;
                        hsi[m] += hry[m]*si1 + hiy[m]*sr1;
                    }
                }
                float v[16];
                #pragma unroll
                for (int m = 0; m < 4; m++) {
                    v[m] = gsr[m]; v[4+m] = gsi[m]; v[8+m] = hsr[m]; v[12+m] = hsi[m];
                }
                float red = bfly16(v, lane);
                store_red16(red, lane, (b_mv*LS + i)*M);
            }
        } else {
            // ---- fp16 read path: 32B evict-hint loads (2 j's per load) ----
            #pragma unroll 1
            for (int t4 = 0; t4 < 4; t4++) {
                int chunk = (bid*4 + t4) & 31;
                int i     = chunk*8 + warp;
                size_t base16 = (size_t)(b_mv*LS + i) * LS * 8;   // halfs
                float gsr[4] = {0,0,0,0}, gsi[4] = {0,0,0,0};
                float hsr[4] = {0,0,0,0}, hsi[4] = {0,0,0,0};
                #pragma unroll
                for (int t = 0; t < 2; t++) {
                    int jp0 = lane + t*64;       // pair index
                    int jp1 = jp0 + 32;
                    ulonglong4 g0 = ld_ef64(d_G16 + base16 + (size_t)jp0*16);
                    ulonglong4 h0 = ld_el64(d_H16 + base16 + (size_t)jp0*16);
                    ulonglong4 g1 = ld_ef64(d_G16 + base16 + (size_t)jp1*16);
                    ulonglong4 h1 = ld_el64(d_H16 + base16 + (size_t)jp1*16);
                    int j00 = jp0*2, j10 = jp1*2;
                    float sa = ssr[j00],   sb = ssi[j00];
                    float sc = ssr[j00+1], sd = ssi[j00+1];
                    float se = ssr[j10],   sf2 = ssi[j10];
                    float sg = ssr[j10+1], sh = ssi[j10+1];
                    upd16u(g0.x, g0.y, sa, sb, gsr, gsi);
                    upd16u(g0.z, g0.w, sc, sd, gsr, gsi);
                    upd16u(h0.x, h0.y, sa, sb, hsr, hsi);
                    upd16u(h0.z, h0.w, sc, sd, hsr, hsi);
                    upd16u(g1.x, g1.y, se, sf2, gsr, gsi);
                    upd16u(g1.z, g1.w, sg, sh, gsr, gsi);
                    upd16u(h1.x, h1.y, se, sf2, hsr, hsi);
                    upd16u(h1.z, h1.w, sg, sh, hsr, hsi);
                }
                float v[16];
                #pragma unroll
                for (int m = 0; m < 4; m++) {
                    v[m] = gsr[m]; v[4+m] = gsi[m]; v[8+m] = hsr[m]; v[12+m] = hsi[m];
                }
                float red = bfly16(v, lane);
                store_red16(red, lane, (b_mv*LS + i)*M);
            }
        }
        __syncthreads();
        if (tid == 0) signal(&d_mvc[step][b_mv]);

        // ------------------ stats (blocks 128..135) ------------------------
        if (bid >= OFF_ST && bid < OFF_ST + NB_ST) {
            if (tid == 0) wait_for(&d_hsc[step], NB_HS);
            __syncthreads();
            int hc = bid - OFF_ST;          // 0..7
            int hh = tid & 63, bs = tid >> 6;
            int h = hc*64 + hh;
            float sum[4] = {0,0,0,0}, sq[4] = {0,0,0,0};
            #pragma unroll 1
            for (int kk = 0; kk < 16; kk++) {
                int b = bs*16 + kk;
                float hv = 0.f;
                #pragma unroll
                for (int kc = 0; kc < KC; kc++)
                    hv += d_hsp[(kc*B + b)*HID + h];
                d_hsv[b*HID + h] = hv;
                #pragma unroll
                for (int m = 0; m < 4; m++) {
                    float v = hv + d_wyW[(b*M + m)*HID + h];
                    sum[m] += v; sq[m] += v*v;
                }
            }
            #pragma unroll
            for (int m = 0; m < 4; m++) {
                ssum[m][bs][hh] = sum[m];
                ssq[m][bs][hh]  = sq[m];
            }
            __syncthreads();
            if (tid < 64) {
                float gm = gamma[hc*64 + tid];
                #pragma unroll
                for (int m = 0; m < 4; m++) {
                    float S = ssum[m][0][tid]+ssum[m][1][tid]+ssum[m][2][tid]+ssum[m][3][tid];
                    float Q = ssq[m][0][tid]+ssq[m][1][tid]+ssq[m][2][tid]+ssq[m][3][tid];
                    float mu  = S * (1.0f/B);
                    float var = Q * (1.0f/B) - mu*mu;
                    int hg = hc*64 + tid;
                    d_mu[m*HID + hg]    = mu;
                    d_scale[m*HID + hg] = gm * rsqrtf(var + 1e-5f);
                }
            }
            __syncthreads();
            if (tid == 0) signal(&d_stc[step]);
        }

        // ------------------ fin (blocks 160..223) --------------------------
        if (bid >= OFF_FIN && bid < OFF_FIN + NB_FIN) {
            int b = bid - OFF_FIN;
            if (tid == 0) {
                wait_for(&d_mvc[step][b], 8);
                wait_for(&d_stc[step], NB_ST);
            }
            __syncthreads();

            // phase 1: per-i loads + sGs/sHs reduction (i = tid)
            int idx = b*LS + tid, o = idx*M;
            float sr = d_sre[idx], si = d_sim[idx];
            float grx[4], gix[4], hrx[4], hix[4];
            {
                float4 g_r = *reinterpret_cast<const float4*>(d_Gsr + o);
                float4 g_i = *reinterpret_cast<const float4*>(d_Gsi + o);
                float4 h_r = *reinterpret_cast<const float4*>(d_Hsr + o);
                float4 h_i = *reinterpret_cast<const float4*>(d_Hsi + o);
                grx[0]=g_r.x; grx[1]=g_r.y; grx[2]=g_r.z; grx[3]=g_r.w;
                gix[0]=g_i.x; gix[1]=g_i.y; gix[2]=g_i.z; gix[3]=g_i.w;
                hrx[0]=h_r.x; hrx[1]=h_r.y; hrx[2]=h_r.z; hrx[3]=h_r.w;
                hix[0]=h_i.x; hix[1]=h_i.y; hix[2]=h_i.z; hix[3]=h_i.w;
                float v[16];
                #pragma unroll
                for (int m = 0; m < 4; m++) {
                    v[m]    = sr*grx[m] + si*gix[m];
                    v[4+m]  = sr*gix[m] - si*grx[m];
                    v[8+m]  = sr*hrx[m] + si*hix[m];
                    v[12+m] = sr*hix[m] - si*hrx[m];
                }
                float red = bfly16(v, lane);
                if ((lane & 1) == 0)
                    wsum[warp][(lane >> 1) & 15] = red;
            }
            __syncthreads();
            if (tid < 16) {
                float s = 0.f;
                #pragma unroll
                for (int w = 0; w < 8; w++) s += wsum[w][tid];
                int m = tid & 3, which = tid >> 2;
                if      (which == 0) sgrS[m] = s;
                else if (which == 1) sgiS[m] = s;
                else if (which == 2) shrS[m] = s;
                else                 shiS[m] = s;
            }

            // phase 2: BN + relu + W2 partial dot (2 h per thread)
            int h0 = tid, h1 = tid + 256;
            float hsv0 = d_hsv[b*HID + h0];
            float hsv1 = d_hsv[b*HID + h1];
            float bt0 = beta[h0], bt1 = beta[h1];
            float w20 = W2[h0],  w21 = W2[h1];
            float r[4];
            #pragma unroll
            for (int m = 0; m < 4; m++) {
                float v0  = hsv0 + d_wyW[(b*M + m)*HID + h0];
                float v1  = hsv1 + d_wyW[(b*M + m)*HID + h1];
                float bn0 = d_scale[m*HID + h0] * (v0 - d_mu[m*HID + h0]) + bt0;
                float bn1 = d_scale[m*HID + h1] * (v1 - d_mu[m*HID + h1]) + bt1;
                r[m] = fmaxf(bn0, 0.f) * w20 + fmaxf(bn1, 0.f) * w21;
            }
            {
                float red = bfly4(r, lane);
                if ((lane & 7) == 0)
                    ws[warp][(lane >> 3) & 3] = red;
            }
            __syncthreads();
            if (tid < 4) {
                float s = 0.f;
                #pragma unroll
                for (int w = 0; w < 8; w++) s += ws[w][tid];
                float rho = 1.0f / (1.0f + expf(-(s + b2[0])));
                rho_s[tid] = rho;
                out[(size_t)2*B*NS1*LS + (b*NSTEP + step)*M + tid] = rho;
                float c = shrS[tid], d = shiS[tid];
                float zr = c*c - d*d, zi = 2.f*c*d;
                fac[tid] = 2.f*zr / (zr*zr + zi*zi);   // Re(2 / sHs^2)
            }
            __syncthreads();

            // phase 3: eta + phi update + next s
            {
                float etanet = 0.f;
                #pragma unroll
                for (int m = 0; m < 4; m++) {
                    float Ar = shrS[m]*grx[m] - shiS[m]*gix[m] - (sgrS[m]*hrx[m] - sgiS[m]*hix[m]);
                    float Ai = shrS[m]*gix[m] + shiS[m]*grx[m] - (sgrS[m]*hix[m] + sgiS[m]*hrx[m]);
                    float imnum = Ai*sr - Ar*si;       // Im(A * conj(s))
                    etanet += fac[m] * imnum * rho_s[m];
                }
                float p = d_phi[idx] - etanet;
                d_phi[idx] = p;
                float sn, cs;
                sincosf(p, &sn, &cs);
                d_sre[idx] = cs;
                d_sim[idx] = sn;
                out[(b*NS1 + step + 1)*LS + tid] = cs;
                out[(size_t)B*NS1*LS + (b*NS1 + step + 1)*LS + tid] = sn;
            }
            __syncthreads();
            if (tid == 0) signal(&d_finc[step][b]);
        }
    }
}

// ---------------- launch -----------------------------------------------------
extern "C" void kernel_launch(void* const* d_in, const int* in_sizes, int n_in,
                              void* d_out, int out_size) {
    const float* phi   = (const float*)d_in[0];
    const float* wr    = (const float*)d_in[1];
    const float* wi    = (const float*)d_in[2];
    const float* y     = (const float*)d_in[3];
    const float* Gr    = (const float*)d_in[4];
    const float* Gi    = (const float*)d_in[5];
    const float* Hr    = (const float*)d_in[6];
    const float* Hi    = (const float*)d_in[7];
    const float* W1    = (const float*)d_in[8];
    const float* b1    = (const float*)d_in[9];
    const float* gamma = (const float*)d_in[10];
    const float* beta  = (const float*)d_in[11];
    const float* W2    = (const float*)d_in[12];
    const float* b2    = (const float*)d_in[13];
    float* out = (float*)d_out;

    k_init<<<2*B, HID>>>(phi, out, wr, wi, y, W1, b1);
    k_steps<<<NPB, 256>>>(Gr, Gi, Hr, Hi, W1, gamma, beta, W2, b2, out);
}

// round 13
// speedup vs baseline: 1.1153x; 1.1153x over previous
#include <cuda_runtime.h>
#include <cuda_fp16.h>
#include <math.h>

#define B 64
#define LS 256
#define M 4
#define LW 256
#define LY 128
#define HID 512
#define NSTEP 6
#define NS1 (NSTEP+1)
#define KC 8           // split-K chunks for hs

#define NPB    512     // persistent blocks (8 per batch), all resident
#define NB_HS  128
#define NB_ST  32
#define NB_FIN 64
#define OFF_ST  NB_HS           // stats blocks 128..159
#define OFF_FIN (NB_HS+NB_ST)   // fin blocks 160..223

// ---------------- scratch (__device__ globals: no allocs allowed) ----------
__device__ float d_phi[B*LS];
__device__ float d_sre[B*LS];
__device__ float d_sim[B*LS];
__device__ float d_Gsr[B*LS*M];
__device__ float d_Gsi[B*LS*M];
__device__ float d_Hsr[B*LS*M];
__device__ float d_Hsi[B*LS*M];
__device__ float d_hsp[KC*B*HID];     // split-K partials of hs
__device__ float d_hsv[B*HID];        // combined hs (written by stats m==0)
__device__ float d_wyW[B*M*HID];
__device__ float d_mu[M*HID];
__device__ float d_scale[M*HID];
__device__ __half d_G16[(size_t)B*LS*LS*M*2];   // packed [gr0..3, gi0..3], streamed
__device__ __half d_H16[(size_t)B*LS*LS*M*2];   // packed, L2-kept (evict_last loads)
__device__ int   d_mvc[NSTEP][B];     // per-b mv completion (8 blocks)
__device__ int   d_finc[NSTEP][B];    // per-b fin completion
__device__ int   d_hsc[NSTEP];
__device__ int   d_stc[NSTEP];

__device__ __forceinline__ int ld_acq(const int* p) {
    int v;
    asm volatile("ld.acquire.gpu.b32 %0, [%1];" : "=r"(v) : "l"(p));
    return v;
}
__device__ __forceinline__ void signal(int* p) {
    __threadfence();
    atomicAdd(p, 1);
}
__device__ __forceinline__ void wait_for(const int* p, int target) {
    while (ld_acq(p) < target) __nanosleep(64);
}

// ---- 32-byte L2 eviction-priority loads/stores (.v4.b64) ----
__device__ __forceinline__ ulonglong4 ld_el64(const void* p) {   // keep in L2
    ulonglong4 v;
    asm volatile("ld.global.L2::evict_last.v4.b64 {%0,%1,%2,%3}, [%4];"
        : "=l"(v.x), "=l"(v.y), "=l"(v.z), "=l"(v.w) : "l"(p));
    return v;
}
__device__ __forceinline__ ulonglong4 ld_ef64(const void* p) {   // stream
    ulonglong4 v;
    asm volatile("ld.global.L2::evict_first.v4.b64 {%0,%1,%2,%3}, [%4];"
        : "=l"(v.x), "=l"(v.y), "=l"(v.z), "=l"(v.w) : "l"(p));
    return v;
}
__device__ __forceinline__ void st_ef64(void* p, ulonglong4 v) { // stream store
    asm volatile("st.global.L2::evict_first.v4.b64 [%0], {%1,%2,%3,%4};"
        :: "l"(p), "l"(v.x), "l"(v.y), "l"(v.z), "l"(v.w) : "memory");
}

__device__ __forceinline__ uint4 pack8f(const float* re, const float* im) {
    __half2 a = __floats2half2_rn(re[0], re[1]);
    __half2 b = __floats2half2_rn(re[2], re[3]);
    __half2 c = __floats2half2_rn(im[0], im[1]);
    __half2 d = __floats2half2_rn(im[2], im[3]);
    uint4 u;
    u.x = *reinterpret_cast<unsigned*>(&a);
    u.y = *reinterpret_cast<unsigned*>(&b);
    u.z = *reinterpret_cast<unsigned*>(&c);
    u.w = *reinterpret_cast<unsigned*>(&d);
    return u;
}
__device__ __forceinline__ ulonglong4 join2(uint4 a, uint4 b) {
    ulonglong4 u;
    u.x = (unsigned long long)a.x | ((unsigned long long)a.y << 32);
    u.y = (unsigned long long)a.z | ((unsigned long long)a.w << 32);
    u.z = (unsigned long long)b.x | ((unsigned long long)b.y << 32);
    u.w = (unsigned long long)b.z | ((unsigned long long)b.w << 32);
    return u;
}
__device__ __forceinline__ void u64tof8(ulonglong4 v, float* f) {
    f[0] = __uint_as_float((unsigned)v.x); f[1] = __uint_as_float((unsigned)(v.x >> 32));
    f[2] = __uint_as_float((unsigned)v.y); f[3] = __uint_as_float((unsigned)(v.y >> 32));
    f[4] = __uint_as_float((unsigned)v.z); f[5] = __uint_as_float((unsigned)(v.z >> 32));
    f[6] = __uint_as_float((unsigned)v.w); f[7] = __uint_as_float((unsigned)(v.w >> 32));
}

// unpack one packed 16B fp16 entry (as two u64) and accumulate matvec partials
__device__ __forceinline__ void upd16u(unsigned long long lo, unsigned long long hi,
                                       float sr, float si, float* ar, float* ai) {
    unsigned u0 = (unsigned)lo, u1 = (unsigned)(lo >> 32);
    unsigned u2 = (unsigned)hi, u3 = (unsigned)(hi >> 32);
    float2 r01 = __half22float2(*reinterpret_cast<__half2*>(&u0));
    float2 r23 = __half22float2(*reinterpret_cast<__half2*>(&u1));
    float2 i01 = __half22float2(*reinterpret_cast<__half2*>(&u2));
    float2 i23 = __half22float2(*reinterpret_cast<__half2*>(&u3));
    float rr[4] = {r01.x, r01.y, r23.x, r23.y};
    float ii[4] = {i01.x, i01.y, i23.x, i23.y};
    #pragma unroll
    for (int m = 0; m < 4; m++) {
        ar[m] += rr[m]*sr - ii[m]*si;
        ai[m] += rr[m]*si + ii[m]*sr;
    }
}

// ---------------- init: phi/s0/out0 + wyW precompute + counter reset -------
__global__ void __launch_bounds__(HID) k_init(const float* __restrict__ phi, float* __restrict__ out,
                                              const float* __restrict__ wr, const float* __restrict__ wi,
                                              const float* __restrict__ y,  const float* __restrict__ W1,
                                              const float* __restrict__ b1) {
    int tid = threadIdx.x;
    if (blockIdx.x < B) {
        int b = blockIdx.x;
        if (b == 0) {
            for (int t = tid; t < NSTEP*B*2 + NSTEP*2; t += HID) {
                if      (t < NSTEP*B)          ((int*)d_mvc)[t] = 0;
                else if (t < 2*NSTEP*B)        ((int*)d_finc)[t - NSTEP*B] = 0;
                else if (t < 2*NSTEP*B+NSTEP)  d_hsc[t - 2*NSTEP*B] = 0;
                else                            d_stc[t - 2*NSTEP*B - NSTEP] = 0;
            }
        }
        if (tid < LS) {
            int idx = b*LS + tid;
            float p = phi[idx];
            d_phi[idx] = p;
            float sn, cs;
            sincosf(p, &sn, &cs);
            d_sre[idx] = cs;
            d_sim[idx] = sn;
            out[(b*NS1)*LS + tid] = cs;
            out[(size_t)B*NS1*LS + (b*NS1)*LS + tid] = sn;
        }
        return;
    }
    int b = blockIdx.x - B;
    __shared__ float4 wy[2*LW + LY];       // 640 x 4 m-values
    for (int d = tid; d < 2*LW + LY; d += HID) {
        float4 v;
        if (d < LW)            v = *reinterpret_cast<const float4*>(wr + (size_t)(b*LW + d)*M);
        else if (d < 2*LW)     v = *reinterpret_cast<const float4*>(wi + (size_t)(b*LW + (d - LW))*M);
        else                   v = *reinterpret_cast<const float4*>(y  + (size_t)(b*LY + (d - 2*LW))*M);
        wy[d] = v;
    }
    __syncthreads();
    float bb = b1[tid];
    float a0 = bb, a1 = bb, a2 = bb, a3 = bb;
    const float* w = W1 + (size_t)(2*LS)*HID + tid;   // rows 512..1151
    #pragma unroll 4
    for (int d = 0; d < 2*LW + LY; d++) {
        float wv = w[(size_t)d * HID];
        float4 q = wy[d];
        a0 += q.x*wv; a1 += q.y*wv; a2 += q.z*wv; a3 += q.w*wv;
    }
    d_wyW[(b*M + 0)*HID + tid] = a0;
    d_wyW[(b*M + 1)*HID + tid] = a1;
    d_wyW[(b*M + 2)*HID + tid] = a2;
    d_wyW[(b*M + 3)*HID + tid] = a3;
}

// ===================== persistent kernel: all 6 steps ========================
__global__ void __launch_bounds__(256, 4)
k_steps(const float* __restrict__ Gr, const float* __restrict__ Gi,
        const float* __restrict__ Hr, const float* __restrict__ Hi,
        const float* __restrict__ W1,
        const float* __restrict__ gamma, const float* __restrict__ beta,
        const float* __restrict__ W2,   const float* __restrict__ b2,
        float* __restrict__ out) {
    int tid = threadIdx.x;
    int bid = blockIdx.x;
    int warp = tid >> 5, lane = tid & 31;

    __shared__ float ssr[LS], ssi[LS];        // s cache (b_mv)
    __shared__ float sf[4][64];               // hs
    __shared__ float ssum[4][64], ssq[4][64]; // stats
    __shared__ float wsum[8][16];             // fin
    __shared__ float ws[8][4];
    __shared__ float rho_s[4], fac[4], sgrS[4], sgiS[4], shrS[4], shiS[4];

    const int b_mv = bid >> 3;                // 8 blocks per batch
    const int k8   = bid & 7;

    for (int step = 0; step < NSTEP; step++) {
        // ------------------ hs (blocks 0..127) — runs first ----------------
        if (bid < NB_HS) {
            int kc = k8, bq = bid >> 3;
            if (step > 0) {
                if (tid == 0) {
                    #pragma unroll
                    for (int bb = 0; bb < 4; bb++)
                        wait_for(&d_finc[step-1][bq*4 + bb], 1);
                }
                __syncthreads();
            }
            {
                int bb = tid >> 6, dd = tid & 63;
                int b = bq*4 + bb, d = kc*64 + dd;
                sf[bb][dd] = (d < LS) ? d_sre[b*LS + d] : d_sim[b*LS + d - LS];
            }
            __syncthreads();
            float a0=0.f,a1=0.f,a2=0.f,a3=0.f;
            float c0=0.f,c1=0.f,c2=0.f,c3=0.f;
            const float* w = W1 + (size_t)(kc*64)*HID + tid;
            #pragma unroll 8
            for (int dd = 0; dd < 64; dd++) {
                float wv0 = w[(size_t)dd * HID];
                float wv1 = w[(size_t)dd * HID + 256];
                float s0 = sf[0][dd], s1 = sf[1][dd], s2 = sf[2][dd], s3 = sf[3][dd];
                a0 += s0*wv0; a1 += s1*wv0; a2 += s2*wv0; a3 += s3*wv0;
                c0 += s0*wv1; c1 += s1*wv1; c2 += s2*wv1; c3 += s3*wv1;
            }
            int b0 = bq*4;
            d_hsp[(kc*B + b0+0)*HID + tid] = a0;
            d_hsp[(kc*B + b0+1)*HID + tid] = a1;
            d_hsp[(kc*B + b0+2)*HID + tid] = a2;
            d_hsp[(kc*B + b0+3)*HID + tid] = a3;
            d_hsp[(kc*B + b0+0)*HID + tid + 256] = c0;
            d_hsp[(kc*B + b0+1)*HID + tid + 256] = c1;
            d_hsp[(kc*B + b0+2)*HID + tid + 256] = c2;
            d_hsp[(kc*B + b0+3)*HID + tid + 256] = c3;
            __syncthreads();
            if (tid == 0) signal(&d_hsc[step]);
        }

        // ------------------ mv: gate on own batch's fin (step-1) -----------
        if (step > 0) {
            if (tid == 0) wait_for(&d_finc[step-1][b_mv], 1);
            __syncthreads();
        }
        ssr[tid] = d_sre[b_mv*LS + tid];
        ssi[tid] = d_sim[b_mv*LS + tid];
        __syncthreads();

        if (step == 0) {
            // ---- fp32 read (32B loads) + fp16 convert-store + accumulate ----
            #pragma unroll 1
            for (int t4 = 0; t4 < 4; t4++) {
                int chunk = (bid*4 + t4) & 31;
                int i     = chunk*8 + warp;
                size_t basef  = (size_t)(b_mv*LS + i) * (LS*M);    // floats
                size_t base16 = (size_t)(b_mv*LS + i) * LS * 8;    // halfs
                float gsr[4] = {0,0,0,0}, gsi[4] = {0,0,0,0};
                float hsr[4] = {0,0,0,0}, hsi[4] = {0,0,0,0};
                #pragma unroll
                for (int t = 0; t < 2; t++) {
                    int jp0 = lane + t*64;     // j-pair index (each pair = 2 j)
                    int jp1 = jp0 + 32;
                    ulonglong4 gru0 = ld_ef64(Gr + basef + (size_t)jp0*8);
                    ulonglong4 giu0 = ld_ef64(Gi + basef + (size_t)jp0*8);
                    ulonglong4 hru0 = ld_ef64(Hr + basef + (size_t)jp0*8);
                    ulonglong4 hiu0 = ld_ef64(Hi + basef + (size_t)jp0*8);
                    ulonglong4 gru1 = ld_ef64(Gr + basef + (size_t)jp1*8);
                    ulonglong4 giu1 = ld_ef64(Gi + basef + (size_t)jp1*8);
                    ulonglong4 hru1 = ld_ef64(Hr + basef + (size_t)jp1*8);
                    ulonglong4 hiu1 = ld_ef64(Hi + basef + (size_t)jp1*8);
                    #pragma unroll
                    for (int p = 0; p < 2; p++) {
                        int jp = p ? jp1 : jp0;
                        float grf[8], gif[8], hrf[8], hif[8];
                        u64tof8(p ? gru1 : gru0, grf);
                        u64tof8(p ? giu1 : giu0, gif);
                        u64tof8(p ? hru1 : hru0, hrf);
                        u64tof8(p ? hiu1 : hiu0, hif);
                        // fp16 stores: G streamed 32B, H default 2x16B
                        st_ef64(d_G16 + base16 + (size_t)jp*16,
                                join2(pack8f(grf, gif), pack8f(grf+4, gif+4)));
                        *reinterpret_cast<uint4*>(d_H16 + base16 + (size_t)jp*16)     = pack8f(hrf, hif);
                        *reinterpret_cast<uint4*>(d_H16 + base16 + (size_t)jp*16 + 8) = pack8f(hrf+4, hif+4);
                        int ja = jp*2;
                        float sra = ssr[ja],   sia = ssi[ja];
                        float srb = ssr[ja+1], sib = ssi[ja+1];
                        #pragma unroll
                        for (int m = 0; m < 4; m++) {
                            gsr[m] += grf[m]*sra - gif[m]*sia;
                            gsi[m] += grf[m]*sia + gif[m]*sra;
                            hsr[m] += hrf[m]*sra - hif[m]*sia;
                            hsi[m] += hrf[m]*sia + hif[m]*sra;
                            gsr[m] += grf[4+m]*srb - gif[4+m]*sib;
                            gsi[m] += grf[4+m]*sib + gif[4+m]*srb;
                            hsr[m] += hrf[4+m]*srb - hif[4+m]*sib;
                            hsi[m] += hrf[4+m]*sib + hif[4+m]*srb;
                        }
                    }
                }
                #pragma unroll
                for (int m = 0; m < 4; m++) {
                    #pragma unroll
                    for (int off = 16; off; off >>= 1) {
                        gsr[m] += __shfl_down_sync(0xffffffffu, gsr[m], off);
                        gsi[m] += __shfl_down_sync(0xffffffffu, gsi[m], off);
                        hsr[m] += __shfl_down_sync(0xffffffffu, hsr[m], off);
                        hsi[m] += __shfl_down_sync(0xffffffffu, hsi[m], off);
                    }
                }
                if (lane == 0) {
                    int o = (b_mv*LS + i)*M;
                    float4 ogr = {gsr[0], gsr[1], gsr[2], gsr[3]};
                    float4 ogi = {gsi[0], gsi[1], gsi[2], gsi[3]};
                    float4 ohr = {hsr[0], hsr[1], hsr[2], hsr[3]};
                    float4 ohi = {hsi[0], hsi[1], hsi[2], hsi[3]};
                    *reinterpret_cast<float4*>(d_Gsr + o) = ogr;
                    *reinterpret_cast<float4*>(d_Gsi + o) = ogi;
                    *reinterpret_cast<float4*>(d_Hsr + o) = ohr;
                    *reinterpret_cast<float4*>(d_Hsi + o) = ohi;
                }
            }
        } else {
            // ---- fp16 read path: 32B evict-hint loads (2 j's per load) ----
            #pragma unroll 1
            for (int t4 = 0; t4 < 4; t4++) {
                int chunk = (bid*4 + t4) & 31;
                int i     = chunk*8 + warp;
                size_t base16 = (size_t)(b_mv*LS + i) * LS * 8;   // halfs
                float gsr[4] = {0,0,0,0}, gsi[4] = {0,0,0,0};
                float hsr[4] = {0,0,0,0}, hsi[4] = {0,0,0,0};
                #pragma unroll
                for (int t = 0; t < 2; t++) {
                    int jp0 = lane + t*64;       // pair index
                    int jp1 = jp0 + 32;
                    ulonglong4 g0 = ld_ef64(d_G16 + base16 + (size_t)jp0*16);
                    ulonglong4 h0 = ld_el64(d_H16 + base16 + (size_t)jp0*16);
                    ulonglong4 g1 = ld_ef64(d_G16 + base16 + (size_t)jp1*16);
                    ulonglong4 h1 = ld_el64(d_H16 + base16 + (size_t)jp1*16);
                    int j00 = jp0*2, j10 = jp1*2;
                    float sa = ssr[j00],   sb = ssi[j00];
                    float sc = ssr[j00+1], sd = ssi[j00+1];
                    float se = ssr[j10],   sf2 = ssi[j10];
                    float sg = ssr[j10+1], sh = ssi[j10+1];
                    upd16u(g0.x, g0.y, sa, sb, gsr, gsi);
                    upd16u(g0.z, g0.w, sc, sd, gsr, gsi);
                    upd16u(h0.x, h0.y, sa, sb, hsr, hsi);
                    upd16u(h0.z, h0.w, sc, sd, hsr, hsi);
                    upd16u(g1.x, g1.y, se, sf2, gsr, gsi);
                    upd16u(g1.z, g1.w, sg, sh, gsr, gsi);
                    upd16u(h1.x, h1.y, se, sf2, hsr, hsi);
                    upd16u(h1.z, h1.w, sg, sh, hsr, hsi);
                }
                #pragma unroll
                for (int m = 0; m < 4; m++) {
                    #pragma unroll
                    for (int off = 16; off; off >>= 1) {
                        gsr[m] += __shfl_down_sync(0xffffffffu, gsr[m], off);
                        gsi[m] += __shfl_down_sync(0xffffffffu, gsi[m], off);
                        hsr[m] += __shfl_down_sync(0xffffffffu, hsr[m], off);
                        hsi[m] += __shfl_down_sync(0xffffffffu, hsi[m], off);
                    }
                }
                if (lane == 0) {
                    int o = (b_mv*LS + i)*M;
                    float4 ogr = {gsr[0], gsr[1], gsr[2], gsr[3]};
                    float4 ogi = {gsi[0], gsi[1], gsi[2], gsi[3]};
                    float4 ohr = {hsr[0], hsr[1], hsr[2], hsr[3]};
                    float4 ohi = {hsi[0], hsi[1], hsi[2], hsi[3]};
                    *reinterpret_cast<float4*>(d_Gsr + o) = ogr;
                    *reinterpret_cast<float4*>(d_Gsi + o) = ogi;
                    *reinterpret_cast<float4*>(d_Hsr + o) = ohr;
                    *reinterpret_cast<float4*>(d_Hsi + o) = ohi;
                }
            }
        }
        __syncthreads();
        if (tid == 0) signal(&d_mvc[step][b_mv]);

        // ------------------ stats (blocks 128..159) ------------------------
        if (bid >= OFF_ST && bid < OFF_FIN) {
            if (tid == 0) wait_for(&d_hsc[step], NB_HS);
            __syncthreads();
            int sb = bid - OFF_ST;          // 0..31
            int hc = sb & 7, m = sb >> 3;
            int hh = tid & 63, bs = tid >> 6;
            int h = hc*64 + hh;
            float sum = 0.f, sq = 0.f;
            #pragma unroll 2
            for (int kk = 0; kk < 16; kk++) {
                int b = bs*16 + kk;
                float hv = 0.f;
                #pragma unroll
                for (int kc = 0; kc < KC; kc++)
                    hv += d_hsp[(kc*B + b)*HID + h];
                if (m == 0) d_hsv[b*HID + h] = hv;   // cache combined hs
                float v = hv + d_wyW[(b*M + m)*HID + h];
                sum += v; sq += v*v;
            }
            ssum[bs][hh] = sum; ssq[bs][hh] = sq;
            __syncthreads();
            if (tid < 64) {
                float S = ssum[0][tid]+ssum[1][tid]+ssum[2][tid]+ssum[3][tid];
                float Q = ssq[0][tid]+ssq[1][tid]+ssq[2][tid]+ssq[3][tid];
                float mu  = S * (1.0f/B);
                float var = Q * (1.0f/B) - mu*mu;
                int hg = hc*64 + tid;
                d_mu[m*HID + hg]    = mu;
                d_scale[m*HID + hg] = gamma[hg] * rsqrtf(var + 1e-5f);
            }
            __syncthreads();
            if (tid == 0) signal(&d_stc[step]);
        }

        // ------------------ fin (blocks 160..223) --------------------------
        if (bid >= OFF_FIN && bid < OFF_FIN + NB_FIN) {
            int b = bid - OFF_FIN;
            if (tid == 0) {
                wait_for(&d_mvc[step][b], 8);
                wait_for(&d_stc[step], NB_ST);
            }
            __syncthreads();

            // phase 1: per-i loads + sGs/sHs reduction (i = tid)
            int idx = b*LS + tid, o = idx*M;
            float sr = d_sre[idx], si = d_sim[idx];
            float grx[4], gix[4], hrx[4], hix[4];
            {
                float4 g_r = *reinterpret_cast<const float4*>(d_Gsr + o);
                float4 g_i = *reinterpret_cast<const float4*>(d_Gsi + o);
                float4 h_r = *reinterpret_cast<const float4*>(d_Hsr + o);
                float4 h_i = *reinterpret_cast<const float4*>(d_Hsi + o);
                grx[0]=g_r.x; grx[1]=g_r.y; grx[2]=g_r.z; grx[3]=g_r.w;
                gix[0]=g_i.x; gix[1]=g_i.y; gix[2]=g_i.z; gix[3]=g_i.w;
                hrx[0]=h_r.x; hrx[1]=h_r.y; hrx[2]=h_r.z; hrx[3]=h_r.w;
                hix[0]=h_i.x; hix[1]=h_i.y; hix[2]=h_i.z; hix[3]=h_i.w;
                float v[16];
                #pragma unroll
                for (int m = 0; m < 4; m++) {
                    v[m]    = sr*grx[m] + si*gix[m];
                    v[4+m]  = sr*gix[m] - si*grx[m];
                    v[8+m]  = sr*hrx[m] + si*hix[m];
                    v[12+m] = sr*hix[m] - si*hrx[m];
                }
                #pragma unroll
                for (int q = 0; q < 16; q++) {
                    #pragma unroll
                    for (int off = 16; off; off >>= 1)
                        v[q] += __shfl_down_sync(0xffffffffu, v[q], off);
                }
                if (lane == 0) {
                    #pragma unroll
                    for (int q = 0; q < 16; q++) wsum[warp][q] = v[q];
                }
            }
            __syncthreads();
            if (tid < 16) {
                float s = 0.f;
                #pragma unroll
                for (int w = 0; w < 8; w++) s += wsum[w][tid];
                int m = tid & 3, which = tid >> 2;
                if      (which == 0) sgrS[m] = s;
                else if (which == 1) sgiS[m] = s;
                else if (which == 2) shrS[m] = s;
                else                 shiS[m] = s;
            }

            // phase 2: BN + relu + W2 partial dot (2 h per thread)
            int h0 = tid, h1 = tid + 256;
            float hsv0 = d_hsv[b*HID + h0];
            float hsv1 = d_hsv[b*HID + h1];
            float bt0 = beta[h0], bt1 = beta[h1];
            float w20 = W2[h0],  w21 = W2[h1];
            float r[4];
            #pragma unroll
            for (int m = 0; m < 4; m++) {
                float v0  = hsv0 + d_wyW[(b*M + m)*HID + h0];
                float v1  = hsv1 + d_wyW[(b*M + m)*HID + h1];
                float bn0 = d_scale[m*HID + h0] * (v0 - d_mu[m*HID + h0]) + bt0;
                float bn1 = d_scale[m*HID + h1] * (v1 - d_mu[m*HID + h1]) + bt1;
                r[m] = fmaxf(bn0, 0.f) * w20 + fmaxf(bn1, 0.f) * w21;
            }
            #pragma unroll
            for (int m = 0; m < 4; m++) {
                #pragma unroll
                for (int off = 16; off; off >>= 1)
                    r[m] += __shfl_down_sync(0xffffffffu, r[m], off);
            }
            if (lane == 0) {
                #pragma unroll
                for (int m = 0; m < 4; m++) ws[warp][m] = r[m];
            }
            __syncthreads();
            if (tid < 4) {
                float s = 0.f;
                #pragma unroll
                for (int w = 0; w < 8; w++) s += ws[w][tid];
                float rho = 1.0f / (1.0f + expf(-(s + b2[0])));
                rho_s[tid] = rho;
                out[(size_t)2*B*NS1*LS + (b*NSTEP + step)*M + tid] = rho;
                float c = shrS[tid], d = shiS[tid];
                float zr = c*c - d*d, zi = 2.f*c*d;
                fac[tid] = 2.f*zr / (zr*zr + zi*zi);   // Re(2 / sHs^2)
            }
            __syncthreads();

            // phase 3: eta + phi update + next s
            {
                float etanet = 0.f;
                #pragma unroll
                for (int m = 0; m < 4; m++) {
                    float Ar = shrS[m]*grx[m] - shiS[m]*gix[m] - (sgrS[m]*hrx[m] - sgiS[m]*hix[m]);
                    float Ai = shrS[m]*gix[m] + shiS[m]*grx[m] - (sgrS[m]*hix[m] + sgiS[m]*hrx[m]);
                    float imnum = Ai*sr - Ar*si;       // Im(A * conj(s))
                    etanet += fac[m] * imnum * rho_s[m];
                }
                float p = d_phi[idx] - etanet;
                d_phi[idx] = p;
                float sn, cs;
                sincosf(p, &sn, &cs);
                d_sre[idx] = cs;
                d_sim[idx] = sn;
                out[(b*NS1 + step + 1)*LS + tid] = cs;
                out[(size_t)B*NS1*LS + (b*NS1 + step + 1)*LS + tid] = sn;
            }
            __syncthreads();
            if (tid == 0) signal(&d_finc[step][b]);
        }
    }
}

// ---------------- launch -----------------------------------------------------
extern "C" void kernel_launch(void* const* d_in, const int* in_sizes, int n_in,
                              void* d_out, int out_size) {
    const float* phi   = (const float*)d_in[0];
    const float* wr    = (const float*)d_in[1];
    const float* wi    = (const float*)d_in[2];
    const float* y     = (const float*)d_in[3];
    const float* Gr    = (const float*)d_in[4];
    const float* Gi    = (const float*)d_in[5];
    const float* Hr    = (const float*)d_in[6];
    const float* Hi    = (const float*)d_in[7];
    const float* W1    = (const float*)d_in[8];
    const float* b1    = (const float*)d_in[9];
    const float* gamma = (const float*)d_in[10];
    const float* beta  = (const float*)d_in[11];
    const float* W2    = (const float*)d_in[12];
    const float* b2    = (const float*)d_in[13];
    float* out = (float*)d_out;

    k_init<<<2*B, HID>>>(phi, out, wr, wi, y, W1, b1);
    k_steps<<<NPB, 256>>>(Gr, Gi, Hr, Hi, W1, gamma, beta, W2, b2, out);
}

// round 14
// speedup vs baseline: 1.2499x; 1.1207x over previous
#include <cuda_runtime.h>
#include <cuda_fp16.h>
#include <math.h>

#define B 64
#define LS 256
#define M 4
#define LW 256
#define LY 128
#define HID 512
#define NSTEP 6
#define NS1 (NSTEP+1)
#define KC 8           // split-K chunks for hs

#define NPB    512     // persistent blocks (8 per batch), all resident
#define NB_HS  128
#define NB_ST  32
#define NB_FIN 64
#define OFF_ST  NB_HS           // stats blocks 128..159
#define OFF_FIN (NB_HS+NB_ST)   // fin blocks 160..223

// ---------------- scratch (__device__ globals: no allocs allowed) ----------
__device__ float d_phi[B*LS];
__device__ float d_sre[B*LS];
__device__ float d_sim[B*LS];
__device__ float d_Gsr[B*LS*M];
__device__ float d_Gsi[B*LS*M];
__device__ float d_Hsr[B*LS*M];
__device__ float d_Hsi[B*LS*M];
__device__ float d_hsp[KC*B*HID];     // split-K partials of hs
__device__ float d_hsv[B*HID];        // combined hs (written by stats m==0)
__device__ float d_wyW[B*M*HID];
__device__ float d_mu[M*HID];
__device__ float d_scale[M*HID];
__device__ __half d_G16[(size_t)B*LS*LS*M*2];   // packed [gr0..3, gi0..3], streamed
__device__ __half d_H16[(size_t)B*LS*LS*M*2];   // packed, L2-kept (evict_last loads)
__device__ int   d_mvc[NSTEP][B];     // per-b mv completion (8 blocks)
__device__ int   d_finc[NSTEP][B];    // per-b fin completion
__device__ int   d_hsc[NSTEP];
__device__ int   d_stc[NSTEP];

__device__ __forceinline__ int ld_acq(const int* p) {
    int v;
    asm volatile("ld.acquire.gpu.b32 %0, [%1];" : "=r"(v) : "l"(p));
    return v;
}
__device__ __forceinline__ void signal(int* p) {
    __threadfence();
    atomicAdd(p, 1);
}
__device__ __forceinline__ void wait_for(const int* p, int target) {
    while (ld_acq(p) < target) __nanosleep(64);
}

// ---- 32-byte L2 eviction-priority loads (.v4.b64 — legal on sm_103a) ----
__device__ __forceinline__ ulonglong4 ld_el64(const __half* p) {   // keep in L2
    ulonglong4 v;
    asm volatile("ld.global.L2::evict_last.v4.b64 {%0,%1,%2,%3}, [%4];"
        : "=l"(v.x), "=l"(v.y), "=l"(v.z), "=l"(v.w) : "l"(p));
    return v;
}
__device__ __forceinline__ ulonglong4 ld_ef64(const __half* p) {   // stream
    ulonglong4 v;
    asm volatile("ld.global.L2::evict_first.v4.b64 {%0,%1,%2,%3}, [%4];"
        : "=l"(v.x), "=l"(v.y), "=l"(v.z), "=l"(v.w) : "l"(p));
    return v;
}

__device__ __forceinline__ uint4 pack8(float4 re, float4 im) {
    __half2 a = __floats2half2_rn(re.x, re.y);
    __half2 b = __floats2half2_rn(re.z, re.w);
    __half2 c = __floats2half2_rn(im.x, im.y);
    __half2 d = __floats2half2_rn(im.z, im.w);
    uint4 u;
    u.x = *reinterpret_cast<unsigned*>(&a);
    u.y = *reinterpret_cast<unsigned*>(&b);
    u.z = *reinterpret_cast<unsigned*>(&c);
    u.w = *reinterpret_cast<unsigned*>(&d);
    return u;
}

// unpack one packed 16B entry (as two u64) and accumulate matvec partials
__device__ __forceinline__ void upd16u(unsigned long long lo, unsigned long long hi,
                                       float sr, float si, float* ar, float* ai) {
    unsigned u0 = (unsigned)lo, u1 = (unsigned)(lo >> 32);
    unsigned u2 = (unsigned)hi, u3 = (unsigned)(hi >> 32);
    float2 r01 = __half22float2(*reinterpret_cast<__half2*>(&u0));
    float2 r23 = __half22float2(*reinterpret_cast<__half2*>(&u1));
    float2 i01 = __half22float2(*reinterpret_cast<__half2*>(&u2));
    float2 i23 = __half22float2(*reinterpret_cast<__half2*>(&u3));
    float rr[4] = {r01.x, r01.y, r23.x, r23.y};
    float ii[4] = {i01.x, i01.y, i23.x, i23.y};
    #pragma unroll
    for (int m = 0; m < 4; m++) {
        ar[m] += rr[m]*sr - ii[m]*si;
        ai[m] += rr[m]*si + ii[m]*sr;
    }
}

// ---------------- init: phi/s0/out0 + wyW precompute + counter reset -------
__global__ void __launch_bounds__(HID) k_init(const float* __restrict__ phi, float* __restrict__ out,
                                              const float* __restrict__ wr, const float* __restrict__ wi,
                                              const float* __restrict__ y,  const float* __restrict__ W1,
                                              const float* __restrict__ b1) {
    int tid = threadIdx.x;
    if (blockIdx.x < B) {
        int b = blockIdx.x;
        if (b == 0) {
            for (int t = tid; t < NSTEP*B*2 + NSTEP*2; t += HID) {
                if      (t < NSTEP*B)          ((int*)d_mvc)[t] = 0;
                else if (t < 2*NSTEP*B)        ((int*)d_finc)[t - NSTEP*B] = 0;
                else if (t < 2*NSTEP*B+NSTEP)  d_hsc[t - 2*NSTEP*B] = 0;
                else                            d_stc[t - 2*NSTEP*B - NSTEP] = 0;
            }
        }
        if (tid < LS) {
            int idx = b*LS + tid;
            float p = phi[idx];
            d_phi[idx] = p;
            float sn, cs;
            sincosf(p, &sn, &cs);
            d_sre[idx] = cs;
            d_sim[idx] = sn;
            out[(b*NS1)*LS + tid] = cs;
            out[(size_t)B*NS1*LS + (b*NS1)*LS + tid] = sn;
        }
        return;
    }
    int b = blockIdx.x - B;
    __shared__ float4 wy[2*LW + LY];       // 640 x 4 m-values
    for (int d = tid; d < 2*LW + LY; d += HID) {
        float4 v;
        if (d < LW)            v = *reinterpret_cast<const float4*>(wr + (size_t)(b*LW + d)*M);
        else if (d < 2*LW)     v = *reinterpret_cast<const float4*>(wi + (size_t)(b*LW + (d - LW))*M);
        else                   v = *reinterpret_cast<const float4*>(y  + (size_t)(b*LY + (d - 2*LW))*M);
        wy[d] = v;
    }
    __syncthreads();
    float bb = b1[tid];
    float a0 = bb, a1 = bb, a2 = bb, a3 = bb;
    const float* w = W1 + (size_t)(2*LS)*HID + tid;   // rows 512..1151
    #pragma unroll 4
    for (int d = 0; d < 2*LW + LY; d++) {
        float wv = w[(size_t)d * HID];
        float4 q = wy[d];
        a0 += q.x*wv; a1 += q.y*wv; a2 += q.z*wv; a3 += q.w*wv;
    }
    d_wyW[(b*M + 0)*HID + tid] = a0;
    d_wyW[(b*M + 1)*HID + tid] = a1;
    d_wyW[(b*M + 2)*HID + tid] = a2;
    d_wyW[(b*M + 3)*HID + tid] = a3;
}

// ===================== persistent kernel: all 6 steps ========================
__global__ void __launch_bounds__(256, 4)
k_steps(const float* __restrict__ Gr, const float* __restrict__ Gi,
        const float* __restrict__ Hr, const float* __restrict__ Hi,
        const float* __restrict__ W1,
        const float* __restrict__ gamma, const float* __restrict__ beta,
        const float* __restrict__ W2,   const float* __restrict__ b2,
        float* __restrict__ out) {
    int tid = threadIdx.x;
    int bid = blockIdx.x;
    int warp = tid >> 5, lane = tid & 31;

    __shared__ float ssr[LS], ssi[LS];        // s cache (b_mv)
    __shared__ float sf[4][64];               // hs
    __shared__ float ssum[4][64], ssq[4][64]; // stats
    __shared__ float wsum[8][16];             // fin
    __shared__ float ws[8][4];
    __shared__ float rho_s[4], fac[4], sgrS[4], sgiS[4], shrS[4], shiS[4];

    const int b_mv = bid >> 3;                // 8 blocks per batch
    const int k8   = bid & 7;

    for (int step = 0; step < NSTEP; step++) {
        // ------------------ hs (blocks 0..127) — runs first ----------------
        if (bid < NB_HS) {
            int kc = k8, bq = bid >> 3;
            if (step > 0) {
                if (tid == 0) {
                    #pragma unroll
                    for (int bb = 0; bb < 4; bb++)
                        wait_for(&d_finc[step-1][bq*4 + bb], 1);
                }
                __syncthreads();
            }
            {
                int bb = tid >> 6, dd = tid & 63;
                int b = bq*4 + bb, d = kc*64 + dd;
                sf[bb][dd] = (d < LS) ? d_sre[b*LS + d] : d_sim[b*LS + d - LS];
            }
            __syncthreads();
            float a0=0.f,a1=0.f,a2=0.f,a3=0.f;
            float c0=0.f,c1=0.f,c2=0.f,c3=0.f;
            const float* w = W1 + (size_t)(kc*64)*HID + tid;
            #pragma unroll 8
            for (int dd = 0; dd < 64; dd++) {
                float wv0 = w[(size_t)dd * HID];
                float wv1 = w[(size_t)dd * HID + 256];
                float s0 = sf[0][dd], s1 = sf[1][dd], s2 = sf[2][dd], s3 = sf[3][dd];
                a0 += s0*wv0; a1 += s1*wv0; a2 += s2*wv0; a3 += s3*wv0;
                c0 += s0*wv1; c1 += s1*wv1; c2 += s2*wv1; c3 += s3*wv1;
            }
            int b0 = bq*4;
            d_hsp[(kc*B + b0+0)*HID + tid] = a0;
            d_hsp[(kc*B + b0+1)*HID + tid] = a1;
            d_hsp[(kc*B + b0+2)*HID + tid] = a2;
            d_hsp[(kc*B + b0+3)*HID + tid] = a3;
            d_hsp[(kc*B + b0+0)*HID + tid + 256] = c0;
            d_hsp[(kc*B + b0+1)*HID + tid + 256] = c1;
            d_hsp[(kc*B + b0+2)*HID + tid + 256] = c2;
            d_hsp[(kc*B + b0+3)*HID + tid + 256] = c3;
            __syncthreads();
            if (tid == 0) signal(&d_hsc[step]);
        }

        // ------------------ mv: gate on own batch's fin (step-1) -----------
        if (step > 0) {
            if (tid == 0) wait_for(&d_finc[step-1][b_mv], 1);
            __syncthreads();
        }
        ssr[tid] = d_sre[b_mv*LS + tid];
        ssi[tid] = d_sim[b_mv*LS + tid];
        __syncthreads();

        if (step == 0) {
            // ---- fp32 read + fp16 convert-store + accumulate ----
            #pragma unroll 1
            for (int t4 = 0; t4 < 4; t4++) {
                int chunk = (bid*4 + t4) & 31;
                int i     = chunk*8 + warp;
                size_t base   = (size_t)(b_mv*LS + i) * (LS*M);
                size_t base16 = (size_t)(b_mv*LS + i) * LS * 8;   // halfs
                float gsr[4] = {0,0,0,0}, gsi[4] = {0,0,0,0};
                float hsr[4] = {0,0,0,0}, hsi[4] = {0,0,0,0};
                #pragma unroll
                for (int t = 0; t < 4; t++) {
                    int j0 = lane + t*64;
                    int j1 = j0 + 32;
                    float4 g_r0 = __ldcs(reinterpret_cast<const float4*>(Gr + base + (size_t)j0*M));
                    float4 g_i0 = __ldcs(reinterpret_cast<const float4*>(Gi + base + (size_t)j0*M));
                    float4 h_r0 = __ldcs(reinterpret_cast<const float4*>(Hr + base + (size_t)j0*M));
                    float4 h_i0 = __ldcs(reinterpret_cast<const float4*>(Hi + base + (size_t)j0*M));
                    float4 g_r1 = __ldcs(reinterpret_cast<const float4*>(Gr + base + (size_t)j1*M));
                    float4 g_i1 = __ldcs(reinterpret_cast<const float4*>(Gi + base + (size_t)j1*M));
                    float4 h_r1 = __ldcs(reinterpret_cast<const float4*>(Hr + base + (size_t)j1*M));
                    float4 h_i1 = __ldcs(reinterpret_cast<const float4*>(Hi + base + (size_t)j1*M));
                    // convert + store packed fp16: G streamed (stcs), H default prio
                    __stcs(reinterpret_cast<uint4*>(d_G16 + base16 + (size_t)j0*8), pack8(g_r0, g_i0));
                    __stcs(reinterpret_cast<uint4*>(d_G16 + base16 + (size_t)j1*8), pack8(g_r1, g_i1));
                    *reinterpret_cast<uint4*>(d_H16 + base16 + (size_t)j0*8) = pack8(h_r0, h_i0);
                    *reinterpret_cast<uint4*>(d_H16 + base16 + (size_t)j1*8) = pack8(h_r1, h_i1);
                    float sr0 = ssr[j0], si0 = ssi[j0];
                    float sr1 = ssr[j1], si1 = ssi[j1];
                    float grx[4] = {g_r0.x, g_r0.y, g_r0.z, g_r0.w};
                    float gix[4] = {g_i0.x, g_i0.y, g_i0.z, g_i0.w};
                    float hrx[4] = {h_r0.x, h_r0.y, h_r0.z, h_r0.w};
                    float hix[4] = {h_i0.x, h_i0.y, h_i0.z, h_i0.w};
                    float gry[4] = {g_r1.x, g_r1.y, g_r1.z, g_r1.w};
                    float giy[4] = {g_i1.x, g_i1.y, g_i1.z, g_i1.w};
                    float hry[4] = {h_r1.x, h_r1.y, h_r1.z, h_r1.w};
                    float hiy[4] = {h_i1.x, h_i1.y, h_i1.z, h_i1.w};
                    #pragma unroll
                    for (int m = 0; m < 4; m++) {
                        gsr[m] += grx[m]*sr0 - gix[m]*si0;
                        gsi[m] += grx[m]*si0 + gix[m]*sr0;
                        hsr[m] += hrx[m]*sr0 - hix[m]*si0;
                        hsi[m] += hrx[m]*si0 + hix[m]*sr0;
                        gsr[m] += gry[m]*sr1 - giy[m]*si1;
                        gsi[m] += gry[m]*si1 + giy[m]*sr1;
                        hsr[m] += hry[m]*sr1 - hiy[m]*si1;
                        hsi[m] += hry[m]*si1 + hiy[m]*sr1;
                    }
                }
                #pragma unroll
                for (int m = 0; m < 4; m++) {
                    #pragma unroll
                    for (int off = 16; off; off >>= 1) {
                        gsr[m] += __shfl_down_sync(0xffffffffu, gsr[m], off);
                        gsi[m] += __shfl_down_sync(0xffffffffu, gsi[m], off);
                        hsr[m] += __shfl_down_sync(0xffffffffu, hsr[m], off);
                        hsi[m] += __shfl_down_sync(0xffffffffu, hsi[m], off);
                    }
                }
                if (lane == 0) {
                    int o = (b_mv*LS + i)*M;
                    float4 ogr = {gsr[0], gsr[1], gsr[2], gsr[3]};
                    float4 ogi = {gsi[0], gsi[1], gsi[2], gsi[3]};
                    float4 ohr = {hsr[0], hsr[1], hsr[2], hsr[3]};
                    float4 ohi = {hsi[0], hsi[1], hsi[2], hsi[3]};
                    *reinterpret_cast<float4*>(d_Gsr + o) = ogr;
                    *reinterpret_cast<float4*>(d_Gsi + o) = ogi;
                    *reinterpret_cast<float4*>(d_Hsr + o) = ohr;
                    *reinterpret_cast<float4*>(d_Hsi + o) = ohi;
                }
            }
        } else {
            // ---- fp16 read path: 32B evict-hint loads (2 j's per load) ----
            #pragma unroll 1
            for (int t4 = 0; t4 < 4; t4++) {
                int chunk = (bid*4 + t4) & 31;
                int i     = chunk*8 + warp;
                size_t base16 = (size_t)(b_mv*LS + i) * LS * 8;   // halfs
                float gsr[4] = {0,0,0,0}, gsi[4] = {0,0,0,0};
                float hsr[4] = {0,0,0,0}, hsi[4] = {0,0,0,0};
                #pragma unroll
                for (int t = 0; t < 2; t++) {
                    int jp0 = lane + t*64;       // pair index
                    int jp1 = jp0 + 32;
                    ulonglong4 g0 = ld_ef64(d_G16 + base16 + (size_t)jp0*16);
                    ulonglong4 h0 = ld_el64(d_H16 + base16 + (size_t)jp0*16);
                    ulonglong4 g1 = ld_ef64(d_G16 + base16 + (size_t)jp1*16);
                    ulonglong4 h1 = ld_el64(d_H16 + base16 + (size_t)jp1*16);
                    int j00 = jp0*2, j10 = jp1*2;
                    float sa = ssr[j00],   sb = ssi[j00];
                    float sc = ssr[j00+1], sd = ssi[j00+1];
                    float se = ssr[j10],   sf2 = ssi[j10];
                    float sg = ssr[j10+1], sh = ssi[j10+1];
                    upd16u(g0.x, g0.y, sa, sb, gsr, gsi);
                    upd16u(g0.z, g0.w, sc, sd, gsr, gsi);
                    upd16u(h0.x, h0.y, sa, sb, hsr, hsi);
                    upd16u(h0.z, h0.w, sc, sd, hsr, hsi);
                    upd16u(g1.x, g1.y, se, sf2, gsr, gsi);
                    upd16u(g1.z, g1.w, sg, sh, gsr, gsi);
                    upd16u(h1.x, h1.y, se, sf2, hsr, hsi);
                    upd16u(h1.z, h1.w, sg, sh, hsr, hsi);
                }
                #pragma unroll
                for (int m = 0; m < 4; m++) {
                    #pragma unroll
                    for (int off = 16; off; off >>= 1) {
                        gsr[m] += __shfl_down_sync(0xffffffffu, gsr[m], off);
                        gsi[m] += __shfl_down_sync(0xffffffffu, gsi[m], off);
                        hsr[m] += __shfl_down_sync(0xffffffffu, hsr[m], off);
                        hsi[m] += __shfl_down_sync(0xffffffffu, hsi[m], off);
                    }
                }
                if (lane == 0) {
                    int o = (b_mv*LS + i)*M;
                    float4 ogr = {gsr[0], gsr[1], gsr[2], gsr[3]};
                    float4 ogi = {gsi[0], gsi[1], gsi[2], gsi[3]};
                    float4 ohr = {hsr[0], hsr[1], hsr[2], hsr[3]};
                    float4 ohi = {hsi[0], hsi[1], hsi[2], hsi[3]};
                    *reinterpret_cast<float4*>(d_Gsr + o) = ogr;
                    *reinterpret_cast<float4*>(d_Gsi + o) = ogi;
                    *reinterpret_cast<float4*>(d_Hsr + o) = ohr;
                    *reinterpret_cast<float4*>(d_Hsi + o) = ohi;
                }
            }
        }
        __syncthreads();
        if (tid == 0) signal(&d_mvc[step][b_mv]);

        // ------------------ stats (blocks 128..159) ------------------------
        if (bid >= OFF_ST && bid < OFF_FIN) {
            if (tid == 0) wait_for(&d_hsc[step], NB_HS);
            __syncthreads();
            int sb = bid - OFF_ST;          // 0..31
            int hc = sb & 7, m = sb >> 3;
            int hh = tid & 63, bs = tid >> 6;
            int h = hc*64 + hh;
            float sum = 0.f, sq = 0.f;
            #pragma unroll 2
            for (int kk = 0; kk < 16; kk++) {
                int b = bs*16 + kk;
                float hv = 0.f;
                #pragma unroll
                for (int kc = 0; kc < KC; kc++)
                    hv += d_hsp[(kc*B + b)*HID + h];
                if (m == 0) d_hsv[b*HID + h] = hv;   // cache combined hs
                float v = hv + d_wyW[(b*M + m)*HID + h];
                sum += v; sq += v*v;
            }
            ssum[bs][hh] = sum; ssq[bs][hh] = sq;
            __syncthreads();
            if (tid < 64) {
                float S = ssum[0][tid]+ssum[1][tid]+ssum[2][tid]+ssum[3][tid];
                float Q = ssq[0][tid]+ssq[1][tid]+ssq[2][tid]+ssq[3][tid];
                float mu  = S * (1.0f/B);
                float var = Q * (1.0f/B) - mu*mu;
                int hg = hc*64 + tid;
                d_mu[m*HID + hg]    = mu;
                d_scale[m*HID + hg] = gamma[hg] * rsqrtf(var + 1e-5f);
            }
            __syncthreads();
            if (tid == 0) signal(&d_stc[step]);
        }

        // ------------------ fin (blocks 160..223) --------------------------
        if (bid >= OFF_FIN && bid < OFF_FIN + NB_FIN) {
            int b = bid - OFF_FIN;
            if (tid == 0) {
                wait_for(&d_mvc[step][b], 8);
                wait_for(&d_stc[step], NB_ST);
            }
            __syncthreads();

            // phase 1: per-i loads + sGs/sHs reduction (i = tid)
            int idx = b*LS + tid, o = idx*M;
            float sr = d_sre[idx], si = d_sim[idx];
            float grx[4], gix[4], hrx[4], hix[4];
            {
                float4 g_r = *reinterpret_cast<const float4*>(d_Gsr + o);
                float4 g_i = *reinterpret_cast<const float4*>(d_Gsi + o);
                float4 h_r = *reinterpret_cast<const float4*>(d_Hsr + o);
                float4 h_i = *reinterpret_cast<const float4*>(d_Hsi + o);
                grx[0]=g_r.x; grx[1]=g_r.y; grx[2]=g_r.z; grx[3]=g_r.w;
                gix[0]=g_i.x; gix[1]=g_i.y; gix[2]=g_i.z; gix[3]=g_i.w;
                hrx[0]=h_r.x; hrx[1]=h_r.y; hrx[2]=h_r.z; hrx[3]=h_r.w;
                hix[0]=h_i.x; hix[1]=h_i.y; hix[2]=h_i.z; hix[3]=h_i.w;
                float v[16];
                #pragma unroll
                for (int m = 0; m < 4; m++) {
                    v[m]    = sr*grx[m] + si*gix[m];
                    v[4+m]  = sr*gix[m] - si*grx[m];
                    v[8+m]  = sr*hrx[m] + si*hix[m];
                    v[12+m] = sr*hix[m] - si*hrx[m];
                }
                #pragma unroll
                for (int q = 0; q < 16; q++) {
                    #pragma unroll
                    for (int off = 16; off; off >>= 1)
                        v[q] += __shfl_down_sync(0xffffffffu, v[q], off);
                }
                if (lane == 0) {
                    #pragma unroll
                    for (int q = 0; q < 16; q++) wsum[warp][q] = v[q];
                }
            }
            __syncthreads();
            if (tid < 16) {
                float s = 0.f;
                #pragma unroll
                for (int w = 0; w < 8; w++) s += wsum[w][tid];
                int m = tid & 3, which = tid >> 2;
                if      (which == 0) sgrS[m] = s;
                else if (which == 1) sgiS[m] = s;
                else if (which == 2) shrS[m] = s;
                else                 shiS[m] = s;
            }

            // phase 2: BN + relu + W2 partial dot (2 h per thread)
            int h0 = tid, h1 = tid + 256;
            float hsv0 = d_hsv[b*HID + h0];
            float hsv1 = d_hsv[b*HID + h1];
            float bt0 = beta[h0], bt1 = beta[h1];
            float w20 = W2[h0],  w21 = W2[h1];
            float r[4];
            #pragma unroll
            for (int m = 0; m < 4; m++) {
                float v0  = hsv0 + d_wyW[(b*M + m)*HID + h0];
                float v1  = hsv1 + d_wyW[(b*M + m)*HID + h1];
                float bn0 = d_scale[m*HID + h0] * (v0 - d_mu[m*HID + h0]) + bt0;
                float bn1 = d_scale[m*HID + h1] * (v1 - d_mu[m*HID + h1]) + bt1;
                r[m] = fmaxf(bn0, 0.f) * w20 + fmaxf(bn1, 0.f) * w21;
            }
            #pragma unroll
            for (int m = 0; m < 4; m++) {
                #pragma unroll
                for (int off = 16; off; off >>= 1)
                    r[m] += __shfl_down_sync(0xffffffffu, r[m], off);
            }
            if (lane == 0) {
                #pragma unroll
                for (int m = 0; m < 4; m++) ws[warp][m] = r[m];
            }
            __syncthreads();
            if (tid < 4) {
                float s = 0.f;
                #pragma unroll
                for (int w = 0; w < 8; w++) s += ws[w][tid];
                float rho = 1.0f / (1.0f + expf(-(s + b2[0])));
                rho_s[tid] = rho;
                out[(size_t)2*B*NS1*LS + (b*NSTEP + step)*M + tid] = rho;
                float c = shrS[tid], d = shiS[tid];
                float zr = c*c - d*d, zi = 2.f*c*d;
                fac[tid] = 2.f*zr / (zr*zr + zi*zi);   // Re(2 / sHs^2)
            }
            __syncthreads();

            // phase 3: eta + phi update + next s
            {
                float etanet = 0.f;
                #pragma unroll
                for (int m = 0; m < 4; m++) {
                    float Ar = shrS[m]*grx[m] - shiS[m]*gix[m] - (sgrS[m]*hrx[m] - sgiS[m]*hix[m]);
                    float Ai = shrS[m]*gix[m] + shiS[m]*grx[m] - (sgrS[m]*hix[m] + sgiS[m]*hrx[m]);
                    float imnum = Ai*sr - Ar*si;       // Im(A * conj(s))
                    etanet += fac[m] * imnum * rho_s[m];
                }
                float p = d_phi[idx] - etanet;
                d_phi[idx] = p;
                float sn, cs;
                sincosf(p, &sn, &cs);
                d_sre[idx] = cs;
                d_sim[idx] = sn;
                out[(b*NS1 + step + 1)*LS + tid] = cs;
                out[(size_t)B*NS1*LS + (b*NS1 + step + 1)*LS + tid] = sn;
            }
            __syncthreads();
            if (tid == 0) signal(&d_finc[step][b]);
        }
    }
}

// ---------------- launch -----------------------------------------------------
extern "C" void kernel_launch(void* const* d_in, const int* in_sizes, int n_in,
                              void* d_out, int out_size) {
    const float* phi   = (const float*)d_in[0];
    const float* wr    = (const float*)d_in[1];
    const float* wi    = (const float*)d_in[2];
    const float* y     = (const float*)d_in[3];
    const float* Gr    = (const float*)d_in[4];
    const float* Gi    = (const float*)d_in[5];
    const float* Hr    = (const float*)d_in[6];
    const float* Hi    = (const float*)d_in[7];
    const float* W1    = (const float*)d_in[8];
    const float* b1    = (const float*)d_in[9];
    const float* gamma = (const float*)d_in[10];
    const float* beta  = (const float*)d_in[11];
    const float* W2    = (const float*)d_in[12];
    const float* b2    = (const float*)d_in[13];
    float* out = (float*)d_out;

    k_init<<<2*B, HID>>>(phi, out, wr, wi, y, W1, b1);
    k_steps<<<NPB, 256>>>(Gr, Gi, Hr, Hi, W1, gamma, beta, W2, b2, out);
}

// round 15
// speedup vs baseline: 1.5198x; 1.2159x over previous
#include <cuda_runtime.h>
#include <cuda_fp16.h>
#include <math.h>

#define B 64
#define LS 256
#define M 4
#define LW 256
#define LY 128
#define HID 512
#define NSTEP 6
#define NS1 (NSTEP+1)
#define KC 8           // split-K chunks for hs

#define NPB    512     // persistent blocks (8 per batch), all resident
#define NB_HS  128
#define NB_ST  32
#define NB_FIN 64
#define OFF_ST  NB_HS           // stats blocks 128..159
#define OFF_FIN (NB_HS+NB_ST)   // fin blocks 160..223

#define NB_CV  512     // conversion blocks in k_init
#define NENT   (B*LS*LS)        // 4,194,304 packed entries per array

// ---------------- scratch (__device__ globals: no allocs allowed) ----------
__device__ float d_phi[B*LS];
__device__ float d_sre[B*LS];
__device__ float d_sim[B*LS];
__device__ float d_Gsr[B*LS*M];
__device__ float d_Gsi[B*LS*M];
__device__ float d_Hsr[B*LS*M];
__device__ float d_Hsi[B*LS*M];
__device__ float d_hsp[KC*B*HID];     // split-K partials of hs
__device__ float d_wyW[B*M*HID];
__device__ float d_mu[M*HID];
__device__ float d_scale[M*HID];
__device__ __half d_G16[(size_t)NENT*8];   // packed [gr0..3, gi0..3], streamed
__device__ __half d_H16[(size_t)NENT*8];   // packed, L2-kept (evict_last loads)
__device__ int   d_mvc[NSTEP][B];     // per-b mv completion (8 blocks)
__device__ int   d_finc[NSTEP][B];    // per-b fin completion
__device__ int   d_hsc[NSTEP];
__device__ int   d_stc[NSTEP];

__device__ __forceinline__ int ld_acq(const int* p) {
    int v;
    asm volatile("ld.acquire.gpu.b32 %0, [%1];" : "=r"(v) : "l"(p));
    return v;
}
__device__ __forceinline__ void signal(int* p) {
    __threadfence();
    atomicAdd(p, 1);
}
__device__ __forceinline__ void wait_for(const int* p, int target) {
    while (ld_acq(p) < target) __nanosleep(64);
}

// ---- 32-byte L2 eviction-priority loads (.v4.b64 — legal on sm_103a) ----
__device__ __forceinline__ ulonglong4 ld_el64(const __half* p) {   // keep in L2
    ulonglong4 v;
    asm volatile("ld.global.L2::evict_last.v4.b64 {%0,%1,%2,%3}, [%4];"
        : "=l"(v.x), "=l"(v.y), "=l"(v.z), "=l"(v.w) : "l"(p));
    return v;
}
__device__ __forceinline__ ulonglong4 ld_ef64(const __half* p) {   // stream
    ulonglong4 v;
    asm volatile("ld.global.L2::evict_first.v4.b64 {%0,%1,%2,%3}, [%4];"
        : "=l"(v.x), "=l"(v.y), "=l"(v.z), "=l"(v.w) : "l"(p));
    return v;
}

__device__ __forceinline__ uint4 pack8(float4 re, float4 im) {
    __half2 a = __floats2half2_rn(re.x, re.y);
    __half2 b = __floats2half2_rn(re.z, re.w);
    __half2 c = __floats2half2_rn(im.x, im.y);
    __half2 d = __floats2half2_rn(im.z, im.w);
    uint4 u;
    u.x = *reinterpret_cast<unsigned*>(&a);
    u.y = *reinterpret_cast<unsigned*>(&b);
    u.z = *reinterpret_cast<unsigned*>(&c);
    u.w = *reinterpret_cast<unsigned*>(&d);
    return u;
}

// unpack one packed 16B entry (as two u64) and accumulate matvec partials
__device__ __forceinline__ void upd16u(unsigned long long lo, unsigned long long hi,
                                       float sr, float si, float* ar, float* ai) {
    unsigned u0 = (unsigned)lo, u1 = (unsigned)(lo >> 32);
    unsigned u2 = (unsigned)hi, u3 = (unsigned)(hi >> 32);
    float2 r01 = __half22float2(*reinterpret_cast<__half2*>(&u0));
    float2 r23 = __half22float2(*reinterpret_cast<__half2*>(&u1));
    float2 i01 = __half22float2(*reinterpret_cast<__half2*>(&u2));
    float2 i23 = __half22float2(*reinterpret_cast<__half2*>(&u3));
    float rr[4] = {r01.x, r01.y, r23.x, r23.y};
    float ii[4] = {i01.x, i01.y, i23.x, i23.y};
    #pragma unroll
    for (int m = 0; m < 4; m++) {
        ar[m] += rr[m]*sr - ii[m]*si;
        ai[m] += rr[m]*si + ii[m]*sr;
    }
}

// ---------------- init: phi/s0/out0 + wyW + counters + fp16 conversion -----
__global__ void __launch_bounds__(HID) k_init(const float* __restrict__ phi, float* __restrict__ out,
                                              const float* __restrict__ wr, const float* __restrict__ wi,
                                              const float* __restrict__ y,  const float* __restrict__ W1,
                                              const float* __restrict__ b1,
                                              const float* __restrict__ Gr, const float* __restrict__ Gi,
                                              const float* __restrict__ Hr, const float* __restrict__ Hi) {
    int tid = threadIdx.x;
    if (blockIdx.x >= 2*B) {
        // ---- conversion blocks: pure streaming fp32 -> packed fp16 ----
        int t0 = (blockIdx.x - 2*B) * HID + tid;     // 0 .. NB_CV*512-1
        const int STRIDE = NB_CV * HID;              // 262144
        const float4* Gr4 = reinterpret_cast<const float4*>(Gr);
        const float4* Gi4 = reinterpret_cast<const float4*>(Gi);
        const float4* Hr4 = reinterpret_cast<const float4*>(Hr);
        const float4* Hi4 = reinterpret_cast<const float4*>(Hi);
        uint4* G4 = reinterpret_cast<uint4*>(d_G16);
        uint4* H4 = reinterpret_cast<uint4*>(d_H16);
        #pragma unroll 4
        for (int k = 0; k < NENT/STRIDE; k++) {
            int idx = t0 + k*STRIDE;
            float4 gr = __ldcs(Gr4 + idx);
            float4 gi = __ldcs(Gi4 + idx);
            float4 hr = __ldcs(Hr4 + idx);
            float4 hi = __ldcs(Hi4 + idx);
            __stcs(G4 + idx, pack8(gr, gi));   // G streamed (evicted)
            H4[idx] = pack8(hr, hi);           // H default prio (L2-resident)
        }
        return;
    }
    if (blockIdx.x < B) {
        int b = blockIdx.x;
        if (b == 0) {
            for (int t = tid; t < NSTEP*B*2 + NSTEP*2; t += HID) {
                if      (t < NSTEP*B)          ((int*)d_mvc)[t] = 0;
                else if (t < 2*NSTEP*B)        ((int*)d_finc)[t - NSTEP*B] = 0;
                else if (t < 2*NSTEP*B+NSTEP)  d_hsc[t - 2*NSTEP*B] = 0;
                else                            d_stc[t - 2*NSTEP*B - NSTEP] = 0;
            }
        }
        if (tid < LS) {
            int idx = b*LS + tid;
            float p = phi[idx];
            d_phi[idx] = p;
            float sn, cs;
            sincosf(p, &sn, &cs);
            d_sre[idx] = cs;
            d_sim[idx] = sn;
            out[(b*NS1)*LS + tid] = cs;
            out[(size_t)B*NS1*LS + (b*NS1)*LS + tid] = sn;
        }
        return;
    }
    int b = blockIdx.x - B;
    __shared__ float4 wy[2*LW + LY];       // 640 x 4 m-values
    for (int d = tid; d < 2*LW + LY; d += HID) {
        float4 v;
        if (d < LW)            v = *reinterpret_cast<const float4*>(wr + (size_t)(b*LW + d)*M);
        else if (d < 2*LW)     v = *reinterpret_cast<const float4*>(wi + (size_t)(b*LW + (d - LW))*M);
        else                   v = *reinterpret_cast<const float4*>(y  + (size_t)(b*LY + (d - 2*LW))*M);
        wy[d] = v;
    }
    __syncthreads();
    float bb = b1[tid];
    float a0 = bb, a1 = bb, a2 = bb, a3 = bb;
    const float* w = W1 + (size_t)(2*LS)*HID + tid;   // rows 512..1151
    #pragma unroll 4
    for (int d = 0; d < 2*LW + LY; d++) {
        float wv = w[(size_t)d * HID];
        float4 q = wy[d];
        a0 += q.x*wv; a1 += q.y*wv; a2 += q.z*wv; a3 += q.w*wv;
    }
    d_wyW[(b*M + 0)*HID + tid] = a0;
    d_wyW[(b*M + 1)*HID + tid] = a1;
    d_wyW[(b*M + 2)*HID + tid] = a2;
    d_wyW[(b*M + 3)*HID + tid] = a3;
}

// ===================== persistent kernel: all 6 steps ========================
__global__ void __launch_bounds__(256, 4)
k_steps(const float* __restrict__ W1,
        const float* __restrict__ gamma, const float* __restrict__ beta,
        const float* __restrict__ W2,   const float* __restrict__ b2,
        float* __restrict__ out) {
    int tid = threadIdx.x;
    int bid = blockIdx.x;
    int warp = tid >> 5, lane = tid & 31;

    __shared__ float ssr[LS], ssi[LS];        // s cache (b_mv)
    __shared__ float sf[4][64];               // hs
    __shared__ float ssum[4][64], ssq[4][64]; // stats
    __shared__ float wsum[8][16];             // fin
    __shared__ float ws[8][4];
    __shared__ float rho_s[4], fac[4], sgrS[4], sgiS[4], shrS[4], shiS[4];

    const int b_mv = bid >> 3;                // 8 blocks per batch
    const int k8   = bid & 7;

    for (int step = 0; step < NSTEP; step++) {
        // ------------------ hs (blocks 0..127) — runs first ----------------
        if (bid < NB_HS) {
            int kc = k8, bq = bid >> 3;
            if (step > 0) {
                if (tid == 0) {
                    #pragma unroll
                    for (int bb = 0; bb < 4; bb++)
                        wait_for(&d_finc[step-1][bq*4 + bb], 1);
                }
                __syncthreads();
            }
            {
                int bb = tid >> 6, dd = tid & 63;
                int b = bq*4 + bb, d = kc*64 + dd;
                sf[bb][dd] = (d < LS) ? d_sre[b*LS + d] : d_sim[b*LS + d - LS];
            }
            __syncthreads();
            float a0=0.f,a1=0.f,a2=0.f,a3=0.f;
            float c0=0.f,c1=0.f,c2=0.f,c3=0.f;
            const float* w = W1 + (size_t)(kc*64)*HID + tid;
            #pragma unroll 8
            for (int dd = 0; dd < 64; dd++) {
                float wv0 = w[(size_t)dd * HID];
                float wv1 = w[(size_t)dd * HID + 256];
                float s0 = sf[0][dd], s1 = sf[1][dd], s2 = sf[2][dd], s3 = sf[3][dd];
                a0 += s0*wv0; a1 += s1*wv0; a2 += s2*wv0; a3 += s3*wv0;
                c0 += s0*wv1; c1 += s1*wv1; c2 += s2*wv1; c3 += s3*wv1;
            }
            int b0 = bq*4;
            d_hsp[(kc*B + b0+0)*HID + tid] = a0;
            d_hsp[(kc*B + b0+1)*HID + tid] = a1;
            d_hsp[(kc*B + b0+2)*HID + tid] = a2;
            d_hsp[(kc*B + b0+3)*HID + tid] = a3;
            d_hsp[(kc*B + b0+0)*HID + tid + 256] = c0;
            d_hsp[(kc*B + b0+1)*HID + tid + 256] = c1;
            d_hsp[(kc*B + b0+2)*HID + tid + 256] = c2;
            d_hsp[(kc*B + b0+3)*HID + tid + 256] = c3;
            __syncthreads();
            if (tid == 0) signal(&d_hsc[step]);
        }

        // ------------------ mv: gate on own batch's fin (step-1) -----------
        if (step > 0) {
            if (tid == 0) wait_for(&d_finc[step-1][b_mv], 1);
            __syncthreads();
        }
        ssr[tid] = d_sre[b_mv*LS + tid];
        ssi[tid] = d_sim[b_mv*LS + tid];
        __syncthreads();

        // ---- fp16 matvec: 32B evict-hint loads (2 j's per load) ----
        #pragma unroll 1
        for (int t4 = 0; t4 < 4; t4++) {
            int chunk = (bid*4 + t4) & 31;
            int i     = chunk*8 + warp;
            size_t base16 = (size_t)(b_mv*LS + i) * LS * 8;   // halfs
            float gsr[4] = {0,0,0,0}, gsi[4] = {0,0,0,0};
            float hsr[4] = {0,0,0,0}, hsi[4] = {0,0,0,0};
            #pragma unroll
            for (int t = 0; t < 2; t++) {
                int jp0 = lane + t*64;       // pair index
                int jp1 = jp0 + 32;
                ulonglong4 g0 = ld_ef64(d_G16 + base16 + (size_t)jp0*16);
                ulonglong4 h0 = ld_el64(d_H16 + base16 + (size_t)jp0*16);
                ulonglong4 g1 = ld_ef64(d_G16 + base16 + (size_t)jp1*16);
                ulonglong4 h1 = ld_el64(d_H16 + base16 + (size_t)jp1*16);
                int j00 = jp0*2, j10 = jp1*2;
                float sa = ssr[j00],   sb = ssi[j00];
                float sc = ssr[j00+1], sd = ssi[j00+1];
                float se = ssr[j10],   sf2 = ssi[j10];
                float sg = ssr[j10+1], sh = ssi[j10+1];
                upd16u(g0.x, g0.y, sa, sb, gsr, gsi);
                upd16u(g0.z, g0.w, sc, sd, gsr, gsi);
                upd16u(h0.x, h0.y, sa, sb, hsr, hsi);
                upd16u(h0.z, h0.w, sc, sd, hsr, hsi);
                upd16u(g1.x, g1.y, se, sf2, gsr, gsi);
                upd16u(g1.z, g1.w, sg, sh, gsr, gsi);
                upd16u(h1.x, h1.y, se, sf2, hsr, hsi);
                upd16u(h1.z, h1.w, sg, sh, hsr, hsi);
            }
            #pragma unroll
            for (int m = 0; m < 4; m++) {
                #pragma unroll
                for (int off = 16; off; off >>= 1) {
                    gsr[m] += __shfl_down_sync(0xffffffffu, gsr[m], off);
                    gsi[m] += __shfl_down_sync(0xffffffffu, gsi[m], off);
                    hsr[m] += __shfl_down_sync(0xffffffffu, hsr[m], off);
                    hsi[m] += __shfl_down_sync(0xffffffffu, hsi[m], off);
                }
            }
            if (lane == 0) {
                int o = (b_mv*LS + i)*M;
                float4 ogr = {gsr[0], gsr[1], gsr[2], gsr[3]};
                float4 ogi = {gsi[0], gsi[1], gsi[2], gsi[3]};
                float4 ohr = {hsr[0], hsr[1], hsr[2], hsr[3]};
                float4 ohi = {hsi[0], hsi[1], hsi[2], hsi[3]};
                *reinterpret_cast<float4*>(d_Gsr + o) = ogr;
                *reinterpret_cast<float4*>(d_Gsi + o) = ogi;
                *reinterpret_cast<float4*>(d_Hsr + o) = ohr;
                *reinterpret_cast<float4*>(d_Hsi + o) = ohi;
            }
        }
        __syncthreads();
        if (tid == 0) signal(&d_mvc[step][b_mv]);

        // ------------------ stats (blocks 128..159) ------------------------
        if (bid >= OFF_ST && bid < OFF_FIN) {
            if (tid == 0) wait_for(&d_hsc[step], NB_HS);
            __syncthreads();
            int sb = bid - OFF_ST;          // 0..31
            int hc = sb & 7, m = sb >> 3;
            int hh = tid & 63, bs = tid >> 6;
            int h = hc*64 + hh;
            float sum = 0.f, sq = 0.f;
            #pragma unroll 2
            for (int kk = 0; kk < 16; kk++) {
                int b = bs*16 + kk;
                float hv = 0.f;
                #pragma unroll
                for (int kc = 0; kc < KC; kc++)
                    hv += d_hsp[(kc*B + b)*HID + h];
                float v = hv + d_wyW[(b*M + m)*HID + h];
                sum += v; sq += v*v;
            }
            ssum[bs][hh] = sum; ssq[bs][hh] = sq;
            __syncthreads();
            if (tid < 64) {
                float S = ssum[0][tid]+ssum[1][tid]+ssum[2][tid]+ssum[3][tid];
                float Q = ssq[0][tid]+ssq[1][tid]+ssq[2][tid]+ssq[3][tid];
                float mu  = S * (1.0f/B);
                float var = Q * (1.0f/B) - mu*mu;
                int hg = hc*64 + tid;
                d_mu[m*HID + hg]    = mu;
                d_scale[m*HID + hg] = gamma[hg] * rsqrtf(var + 1e-5f);
            }
            __syncthreads();
            if (tid == 0) signal(&d_stc[step]);
        }

        // ------------------ fin (blocks 160..223) --------------------------
        if (bid >= OFF_FIN && bid < OFF_FIN + NB_FIN) {
            int b = bid - OFF_FIN;
            if (tid == 0) {
                wait_for(&d_mvc[step][b], 8);
                wait_for(&d_stc[step], NB_ST);
            }
            __syncthreads();

            // phase 1: per-i loads + sGs/sHs reduction (i = tid)
            int idx = b*LS + tid, o = idx*M;
            float sr = d_sre[idx], si = d_sim[idx];
            float grx[4], gix[4], hrx[4], hix[4];
            {
                float4 g_r = *reinterpret_cast<const float4*>(d_Gsr + o);
                float4 g_i = *reinterpret_cast<const float4*>(d_Gsi + o);
                float4 h_r = *reinterpret_cast<const float4*>(d_Hsr + o);
                float4 h_i = *reinterpret_cast<const float4*>(d_Hsi + o);
                grx[0]=g_r.x; grx[1]=g_r.y; grx[2]=g_r.z; grx[3]=g_r.w;
                gix[0]=g_i.x; gix[1]=g_i.y; gix[2]=g_i.z; gix[3]=g_i.w;
                hrx[0]=h_r.x; hrx[1]=h_r.y; hrx[2]=h_r.z; hrx[3]=h_r.w;
                hix[0]=h_i.x; hix[1]=h_i.y; hix[2]=h_i.z; hix[3]=h_i.w;
                float v[16];
                #pragma unroll
                for (int m = 0; m < 4; m++) {
                    v[m]    = sr*grx[m] + si*gix[m];
                    v[4+m]  = sr*gix[m] - si*grx[m];
                    v[8+m]  = sr*hrx[m] + si*hix[m];
                    v[12+m] = sr*hix[m] - si*hrx[m];
                }
                #pragma unroll
                for (int q = 0; q < 16; q++) {
                    #pragma unroll
                    for (int off = 16; off; off >>= 1)
                        v[q] += __shfl_down_sync(0xffffffffu, v[q], off);
                }
                if (lane == 0) {
                    #pragma unroll
                    for (int q = 0; q < 16; q++) wsum[warp][q] = v[q];
                }
            }
            __syncthreads();
            if (tid < 16) {
                float s = 0.f;
                #pragma unroll
                for (int w = 0; w < 8; w++) s += wsum[w][tid];
                int m = tid & 3, which = tid >> 2;
                if      (which == 0) sgrS[m] = s;
                else if (which == 1) sgiS[m] = s;
                else if (which == 2) shrS[m] = s;
                else                 shiS[m] = s;
            }

            // phase 2: BN + relu + W2 partial dot (2 h per thread)
            int h0 = tid, h1 = tid + 256;
            float hsv0 = 0.f, hsv1 = 0.f;
            #pragma unroll
            for (int kc = 0; kc < KC; kc++) {
                hsv0 += d_hsp[(kc*B + b)*HID + h0];
                hsv1 += d_hsp[(kc*B + b)*HID + h1];
            }
            float bt0 = beta[h0], bt1 = beta[h1];
            float w20 = W2[h0],  w21 = W2[h1];
            float r[4];
            #pragma unroll
            for (int m = 0; m < 4; m++) {
                float v0  = hsv0 + d_wyW[(b*M + m)*HID + h0];
                float v1  = hsv1 + d_wyW[(b*M + m)*HID + h1];
                float bn0 = d_scale[m*HID + h0] * (v0 - d_mu[m*HID + h0]) + bt0;
                float bn1 = d_scale[m*HID + h1] * (v1 - d_mu[m*HID + h1]) + bt1;
                r[m] = fmaxf(bn0, 0.f) * w20 + fmaxf(bn1, 0.f) * w21;
            }
            #pragma unroll
            for (int m = 0; m < 4; m++) {
                #pragma unroll
                for (int off = 16; off; off >>= 1)
                    r[m] += __shfl_down_sync(0xffffffffu, r[m], off);
            }
            if (lane == 0) {
                #pragma unroll
                for (int m = 0; m < 4; m++) ws[warp][m] = r[m];
            }
            __syncthreads();
            if (tid < 4) {
                float s = 0.f;
                #pragma unroll
                for (int w = 0; w < 8; w++) s += ws[w][tid];
                float rho = 1.0f / (1.0f + expf(-(s + b2[0])));
                rho_s[tid] = rho;
                out[(size_t)2*B*NS1*LS + (b*NSTEP + step)*M + tid] = rho;
                float c = shrS[tid], d = shiS[tid];
                float zr = c*c - d*d, zi = 2.f*c*d;
                fac[tid] = 2.f*zr / (zr*zr + zi*zi);   // Re(2 / sHs^2)
            }
            __syncthreads();

            // phase 3: eta + phi update + next s
            {
                float etanet = 0.f;
                #pragma unroll
                for (int m = 0; m < 4; m++) {
                    float Ar = shrS[m]*grx[m] - shiS[m]*gix[m] - (sgrS[m]*hrx[m] - sgiS[m]*hix[m]);
                    float Ai = shrS[m]*gix[m] + shiS[m]*grx[m] - (sgrS[m]*hix[m] + sgiS[m]*hrx[m]);
                    float imnum = Ai*sr - Ar*si;       // Im(A * conj(s))
                    etanet += fac[m] * imnum * rho_s[m];
                }
                float p = d_phi[idx] - etanet;
                d_phi[idx] = p;
                float sn, cs;
                sincosf(p, &sn, &cs);
                d_sre[idx] = cs;
                d_sim[idx] = sn;
                out[(b*NS1 + step + 1)*LS + tid] = cs;
                out[(size_t)B*NS1*LS + (b*NS1 + step + 1)*LS + tid] = sn;
            }
            __syncthreads();
            if (tid == 0) signal(&d_finc[step][b]);
        }
    }
}

// ---------------- launch -----------------------------------------------------
extern "C" void kernel_launch(void* const* d_in, const int* in_sizes, int n_in,
                              void* d_out, int out_size) {
    const float* phi   = (const float*)d_in[0];
    const float* wr    = (const float*)d_in[1];
    const float* wi    = (const float*)d_in[2];
    const float* y     = (const float*)d_in[3];
    const float* Gr    = (const float*)d_in[4];
    const float* Gi    = (const float*)d_in[5];
    const float* Hr    = (const float*)d_in[6];
    const float* Hi    = (const float*)d_in[7];
    const float* W1    = (const float*)d_in[8];
    const float* b1    = (const float*)d_in[9];
    const float* gamma = (const float*)d_in[10];
    const float* beta  = (const float*)d_in[11];
    const float* W2    = (const float*)d_in[12];
    const float* b2    = (const float*)d_in[13];
    float* out = (float*)d_out;

    k_init<<<2*B + NB_CV, HID>>>(phi, out, wr, wi, y, W1, b1, Gr, Gi, Hr, Hi);
    k_steps<<<NPB, 256>>>(W1, gamma, beta, W2, b2, out);
}